// round 10
// baseline (speedup 1.0000x reference)
#include <cuda_runtime.h>
#include <cuda_fp16.h>
#include <math.h>
#include <stdint.h>

// Problem constants
#define BB   4
#define SS   2048
#define DD   1024
#define HH   16
#define HD   64
#define FF   4096
#define NR   (BB*SS)          // 8192 rows
#define EPSL 1e-5f

// ---------------- scratch (device globals; no allocation allowed) ----------
__device__ float g_q [NR*DD];        // Wo output fp32
__device__ float g_k [NR*DD];        // FF2 output fp32
__device__ float g_r [NR*DD];        // LN1 output fp32

// fp16 activations (single term)
__device__ __align__(16) __half g_xh  [NR*DD];
__device__ __align__(16) __half g_qkv [(size_t)NR*3*DD];   // fused QKV output
__device__ __align__(16) __half g_ah  [NR*DD];
__device__ __align__(16) __half g_rh  [NR*DD];
__device__ __align__(16) __half g_ffh [(size_t)NR*FF];

// fp16 weights. QKV concatenated along N: [DD, 3*DD]
__device__ __align__(16) __half g_wqkv[DD*3*DD];
__device__ __align__(16) __half g_wo  [DD*DD];
__device__ __align__(16) __half g_w1  [(size_t)DD*FF];
__device__ __align__(16) __half g_w2  [(size_t)DD*FF];

// ---------------- asm helpers ------------------------------------------------
#define LDSM_X4(R0,R1,R2,R3,ADDR) \
    asm volatile("ldmatrix.sync.aligned.m8n8.x4.shared.b16 {%0,%1,%2,%3},[%4];" \
        : "=r"(R0),"=r"(R1),"=r"(R2),"=r"(R3) : "r"(ADDR))

#define LDSM_X4_T(R0,R1,R2,R3,ADDR) \
    asm volatile("ldmatrix.sync.aligned.m8n8.x4.trans.shared.b16 {%0,%1,%2,%3},[%4];" \
        : "=r"(R0),"=r"(R1),"=r"(R2),"=r"(R3) : "r"(ADDR))

#define MMAH(D,A0,A1,A2,A3,B0,B1) \
    asm volatile("mma.sync.aligned.m16n8k16.row.col.f32.f16.f16.f32 " \
        "{%0,%1,%2,%3},{%4,%5,%6,%7},{%8,%9},{%0,%1,%2,%3};" \
        : "+f"(D[0]),"+f"(D[1]),"+f"(D[2]),"+f"(D[3]) \
        : "r"(A0),"r"(A1),"r"(A2),"r"(A3),"r"(B0),"r"(B1))

__device__ __forceinline__ void cp16(uint32_t dst, const void* src) {
    asm volatile("cp.async.cg.shared.global [%0],[%1],16;" :: "r"(dst), "l"(src));
}
#define CP_COMMIT() asm volatile("cp.async.commit_group;" ::: "memory")
#define CP_WAIT0()  asm volatile("cp.async.wait_group 0;" ::: "memory")
#define CP_WAIT1()  asm volatile("cp.async.wait_group 1;" ::: "memory")

__device__ __forceinline__ uint32_t pack_h2(float a, float b) {
    __half2 h = __floats2half2_rn(a, b);
    return *reinterpret_cast<uint32_t*>(&h);
}

// fast exp on the FMA pipe. x <= 0 expected. ~2e-6 rel err.
__device__ __forceinline__ float expf_fast(float x) {
    float y = fmaxf(x * 1.44269504088896f, -126.f);
    float fl = floorf(y);
    float f = y - fl;
    float p = 1.54653240e-4f;
    p = fmaf(p, f, 1.33335581e-3f);
    p = fmaf(p, f, 9.61812910e-3f);
    p = fmaf(p, f, 5.55041086e-2f);
    p = fmaf(p, f, 2.40226507e-1f);
    p = fmaf(p, f, 6.93147181e-1f);
    p = fmaf(p, f, 1.0f);
    int ei = (int)fl;
    float sc = __int_as_float((ei + 127) << 23);
    return p * sc;
}

// ---------------- one-shot fp32 -> fp16 convert, all tensors -----------------
struct SplitSeg {
    const float* src;
    __half* h;
    int nblk;         // blocks of 1024 elems
    int cols;         // source row length
    int stride;       // dst row stride
    int off;          // dst column offset
};
struct SplitArgs { SplitSeg s[7]; };

__global__ __launch_bounds__(256)
void split_all_kernel(SplitArgs a)
{
    int blk = blockIdx.x;
    int i = 0;
    while (blk >= a.s[i].nblk) { blk -= a.s[i].nblk; i++; }
    SplitSeg sg = a.s[i];

    int e   = blk * 1024 + threadIdx.x * 4;
    int row = e / sg.cols;
    int col = e - row * sg.cols;
    size_t d = (size_t)row * sg.stride + sg.off + col;

    float4 v = *(const float4*)(sg.src + (size_t)e);
    float av[4] = {v.x, v.y, v.z, v.w};
    uint2 uh;
    __half* hp = (__half*)&uh;
    #pragma unroll
    for (int j = 0; j < 4; j++) hp[j] = __float2half_rn(av[j]);
    *(uint2*)(sg.h + d) = uh;
}

// ---------------- HMMA GEMM: BM=128, BN=256, warp tile 64x64 -----------------
// C[M,N] = A[M,K] @ B[K,N], fp16 in, fp32 accum. 256 threads, 8 warps (2x4).
// stage: A 128x32 @pitch80 = 10240 B, B 32x256 @pitch528 = 16896 B -> 27136 B.
// 3 stages = 81408 B, 1 CTA/SM. Pitches mod 128 = {80,16}: ldmatrix
// conflict-free (8 row-phases distinct).
#define PAB 80
#define PBB 528
#define STG4 27136
#define NST 3

__device__ __forceinline__ void load_stage(
    uint32_t sb,
    const __half* __restrict__ Ah,
    const __half* __restrict__ Bh, int K, int N, int tid)
{
    // A: 512 chunks
    #pragma unroll
    for (int it = 0; it < 2; it++) {
        int idx = it * 256 + tid;
        int r = idx >> 2, c4 = idx & 3;
        cp16(sb + r * PAB + c4 * 16, Ah + (size_t)r * K + c4 * 8);
    }
    // B: 1024 chunks (32 rows x 32 chunks)
    #pragma unroll
    for (int it = 0; it < 4; it++) {
        int idx = it * 256 + tid;
        int r = idx >> 5, c16 = idx & 31;
        cp16(sb + 10240 + r * PBB + c16 * 16, Bh + (size_t)r * N + c16 * 8);
    }
}

// EPI: 0 plain fp32 | 1 bias+relu -> fp16 | 2 bias -> fp32 | 3 plain -> fp16
template<int EPI>
__global__ __launch_bounds__(256)
void hgemm4_kernel(int M, int N, int K,
                   const __half* __restrict__ Ah,
                   const __half* __restrict__ Bh,
                   const float* __restrict__ bias,
                   float* __restrict__ C,
                   __half* __restrict__ Ch)
{
    extern __shared__ __align__(16) char smem[];
    uint32_t sb = (uint32_t)__cvta_generic_to_shared(smem);

    int tid  = threadIdx.x;
    int lane = tid & 31;
    int warp = tid >> 5;
    int wm = warp & 1;            // 2 warps along M -> 64 rows each
    int wn = warp >> 1;           // 4 warps along N -> 64 cols each
    int row0 = blockIdx.y * 128;
    int col0 = blockIdx.x * 256;

    const __half* Ahb = Ah + (size_t)row0 * K;
    const __half* Bhb = Bh + col0;

    float acc[4][8][4];
    #pragma unroll
    for (int i = 0; i < 4; i++)
        #pragma unroll
        for (int j = 0; j < 8; j++)
            #pragma unroll
            for (int c = 0; c < 4; c++) acc[i][j][c] = 0.f;

    int NT = K / 32;

    #pragma unroll
    for (int i = 0; i < NST - 1; i++) {
        load_stage(sb + i * STG4, Ahb + i * 32, Bhb + (size_t)(i * 32) * N, K, N, tid);
        CP_COMMIT();
    }

    for (int kt = 0; kt < NT; kt++) {
        CP_WAIT1();
        __syncthreads();

        int nk = kt + NST - 1;
        if (nk < NT) {
            load_stage(sb + (nk % NST) * STG4, Ahb + nk * 32,
                       Bhb + (size_t)(nk * 32) * N, K, N, tid);
        }
        CP_COMMIT();

        uint32_t st = sb + (kt % NST) * STG4;
        #pragma unroll
        for (int kk = 0; kk < 32; kk += 16) {
            uint32_t ahi[4][4], bfr[8][2];

            #pragma unroll
            for (int mi = 0; mi < 4; mi++) {
                int r = wm * 64 + mi * 16 + (lane & 15);
                int c = kk + (lane >> 4) * 8;
                LDSM_X4(ahi[mi][0], ahi[mi][1], ahi[mi][2], ahi[mi][3], st + r * PAB + c * 2);
            }
            #pragma unroll
            for (int cb = 0; cb < 4; cb++) {
                int r = kk + (lane & 15);
                int c = wn * 64 + cb * 16 + (lane >> 4) * 8;
                uint32_t bh = st + 10240 + r * PBB + c * 2;
                LDSM_X4_T(bfr[cb*2][0], bfr[cb*2][1], bfr[cb*2+1][0], bfr[cb*2+1][1], bh);
            }

            #pragma unroll
            for (int mi = 0; mi < 4; mi++)
                #pragma unroll
                for (int ni = 0; ni < 8; ni++)
                    MMAH(acc[mi][ni], ahi[mi][0], ahi[mi][1], ahi[mi][2], ahi[mi][3],
                         bfr[ni][0], bfr[ni][1]);
        }
    }

    // epilogue
    int g = lane >> 2, t = lane & 3;
    #pragma unroll
    for (int mi = 0; mi < 4; mi++) {
        #pragma unroll
        for (int ni = 0; ni < 8; ni++) {
            int r = row0 + wm * 64 + mi * 16 + g;
            int c = col0 + wn * 64 + ni * 8 + t * 2;
            float v0 = acc[mi][ni][0], v1 = acc[mi][ni][1];
            float v2 = acc[mi][ni][2], v3 = acc[mi][ni][3];

            if (EPI == 1 || EPI == 2) {
                float bz0 = bias[c], bz1 = bias[c + 1];
                v0 += bz0; v1 += bz1; v2 += bz0; v3 += bz1;
            }
            if (EPI == 1) {
                v0 = fmaxf(v0, 0.f); v1 = fmaxf(v1, 0.f);
                v2 = fmaxf(v2, 0.f); v3 = fmaxf(v3, 0.f);
            }

            if (EPI == 0 || EPI == 2) {
                *(float2*)&C[(size_t)r * N + c]       = make_float2(v0, v1);
                *(float2*)&C[(size_t)(r + 8) * N + c] = make_float2(v2, v3);
            } else {
                *(uint32_t*)&Ch[(size_t)r * N + c]       = pack_h2(v0, v1);
                *(uint32_t*)&Ch[(size_t)(r + 8) * N + c] = pack_h2(v2, v3);
            }
        }
    }
}

// ---------------- flash attention: fp16 single-term, cp.async ----------------
// QKV input fused layout [NR, 3*DD]; Q at col 0, K at DD, V at 2*DD.
#define QKVS (3*DD)

__device__ __forceinline__ void load_kv(uint32_t buf,
                                        const __half* __restrict__ KhB,
                                        const __half* __restrict__ VhB,
                                        int k0, int tid)
{
    #pragma unroll
    for (int it = 0; it < 4; it++) {
        int idx = it * 128 + tid;
        int r = idx >> 3, c = idx & 7;
        cp16(buf + r * 144 + c * 16,        KhB + (size_t)(k0 + r) * QKVS + c * 8);
        cp16(buf + 9216 + r * 144 + c * 16, VhB + (size_t)(k0 + r) * QKVS + c * 8);
    }
}

__global__ __launch_bounds__(128)
void attn_f16_kernel(const __half* __restrict__ QKV,
                     const int* __restrict__ vlen,
                     __half* __restrict__ Oh)
{
    __shared__ __align__(16) char smem[36864];
    uint32_t sb = (uint32_t)__cvta_generic_to_shared(smem);

    int tid  = threadIdx.x;
    int lane = tid & 31;
    int warp = tid >> 5;
    int g    = lane >> 2;
    int t    = lane & 3;

    int bh = blockIdx.y;
    int b  = bh >> 4;
    int h  = bh & 15;
    int q0 = blockIdx.x * 64;
    int vl = vlen[b];

    size_t base = (size_t)(b * SS) * QKVS + h * HD;
    const __half* QhB = QKV + base + (size_t)q0 * QKVS;
    const __half* KhB = QKV + base + DD;
    const __half* VhB = QKV + base + 2 * DD;

    // stage Q
    #pragma unroll
    for (int it = 0; it < 4; it++) {
        int idx = it * 128 + tid;
        int r = idx >> 3, c = idx & 7;
        cp16(sb + r * 144 + c * 16, QhB + (size_t)r * QKVS + c * 8);
    }
    CP_COMMIT(); CP_WAIT0();
    __syncthreads();

    uint32_t qh[4][4];
    #pragma unroll
    for (int kk = 0; kk < 4; kk++) {
        int r = warp * 16 + (lane & 15);
        int c = kk * 16 + (lane >> 4) * 8;
        LDSM_X4(qh[kk][0], qh[kk][1], qh[kk][2], qh[kk][3], sb + r * 144 + c * 2);
    }
    __syncthreads();

    float o[8][4];
    #pragma unroll
    for (int i = 0; i < 8; i++)
        #pragma unroll
        for (int c = 0; c < 4; c++) o[i][c] = 0.f;
    float m0 = -1e30f, m1 = -1e30f, l0 = 0.f, l1 = 0.f;

    int nkt = (vl + 63) >> 6;

    load_kv(sb, KhB, VhB, 0, tid);
    CP_COMMIT();

    for (int kt = 0; kt < nkt; kt++) {
        __syncthreads();
        if (kt + 1 < nkt)
            load_kv(sb + ((kt + 1) & 1) * 18432, KhB, VhB, (kt + 1) * 64, tid);
        CP_COMMIT();
        CP_WAIT1();
        __syncthreads();

        uint32_t cur = sb + (kt & 1) * 18432;
        int k0 = kt * 64;

        float s[8][4];
        #pragma unroll
        for (int i = 0; i < 8; i++)
            #pragma unroll
            for (int c = 0; c < 4; c++) s[i][c] = 0.f;

        #pragma unroll
        for (int kk = 0; kk < 4; kk++) {
            #pragma unroll
            for (int nb = 0; nb < 4; nb++) {
                int r = nb * 16 + (lane & 15);
                int c = kk * 16 + (lane >> 4) * 8;
                uint32_t kh0, kh1, kh2, kh3;
                LDSM_X4(kh0, kh1, kh2, kh3, cur + r * 144 + c * 2);
                MMAH(s[2*nb],   qh[kk][0], qh[kk][1], qh[kk][2], qh[kk][3], kh0, kh2);
                MMAH(s[2*nb+1], qh[kk][0], qh[kk][1], qh[kk][2], qh[kk][3], kh1, kh3);
            }
        }

        #pragma unroll
        for (int nb = 0; nb < 8; nb++) {
            int c0 = k0 + nb * 8 + 2 * t;
            int c1 = c0 + 1;
            s[nb][0] = (c0 < vl) ? s[nb][0] * 0.125f : -1e30f;
            s[nb][1] = (c1 < vl) ? s[nb][1] * 0.125f : -1e30f;
            s[nb][2] = (c0 < vl) ? s[nb][2] * 0.125f : -1e30f;
            s[nb][3] = (c1 < vl) ? s[nb][3] * 0.125f : -1e30f;
        }

        float tm0 = -1e30f, tm1 = -1e30f;
        #pragma unroll
        for (int nb = 0; nb < 8; nb++) {
            tm0 = fmaxf(tm0, fmaxf(s[nb][0], s[nb][1]));
            tm1 = fmaxf(tm1, fmaxf(s[nb][2], s[nb][3]));
        }
        tm0 = fmaxf(tm0, __shfl_xor_sync(0xffffffffu, tm0, 1));
        tm0 = fmaxf(tm0, __shfl_xor_sync(0xffffffffu, tm0, 2));
        tm1 = fmaxf(tm1, __shfl_xor_sync(0xffffffffu, tm1, 1));
        tm1 = fmaxf(tm1, __shfl_xor_sync(0xffffffffu, tm1, 2));

        float mn0 = fmaxf(m0, tm0);
        float mn1 = fmaxf(m1, tm1);
        float al0 = expf_fast(m0 - mn0);
        float al1 = expf_fast(m1 - mn1);

        uint32_t pA[4][4];
        float ls0 = 0.f, ls1 = 0.f;
        #pragma unroll
        for (int nb = 0; nb < 8; nb++) {
            float p0 = expf_fast(s[nb][0] - mn0);
            float p1 = expf_fast(s[nb][1] - mn0);
            float p2 = expf_fast(s[nb][2] - mn1);
            float p3 = expf_fast(s[nb][3] - mn1);
            ls0 += p0 + p1;
            ls1 += p2 + p3;
            int ks = nb >> 1;
            int hf = (nb & 1) * 2;
            pA[ks][hf + 0] = pack_h2(p0, p1);
            pA[ks][hf + 1] = pack_h2(p2, p3);
        }
        ls0 += __shfl_xor_sync(0xffffffffu, ls0, 1);
        ls0 += __shfl_xor_sync(0xffffffffu, ls0, 2);
        ls1 += __shfl_xor_sync(0xffffffffu, ls1, 1);
        ls1 += __shfl_xor_sync(0xffffffffu, ls1, 2);

        l0 = l0 * al0 + ls0;
        l1 = l1 * al1 + ls1;
        m0 = mn0;
        m1 = mn1;

        #pragma unroll
        for (int nb = 0; nb < 8; nb++) {
            o[nb][0] *= al0; o[nb][1] *= al0;
            o[nb][2] *= al1; o[nb][3] *= al1;
        }

        #pragma unroll
        for (int kk = 0; kk < 4; kk++) {
            uint32_t a0 = pA[kk][0], a1 = pA[kk][1], a2 = pA[kk][2], a3 = pA[kk][3];
            #pragma unroll
            for (int nb = 0; nb < 4; nb++) {
                int r = kk * 16 + (lane & 15);
                int c = nb * 16 + (lane >> 4) * 8;
                uint32_t vh0, vh1, vh2, vh3;
                LDSM_X4_T(vh0, vh1, vh2, vh3, cur + 9216 + r * 144 + c * 2);
                MMAH(o[2*nb],   a0, a1, a2, a3, vh0, vh1);
                MMAH(o[2*nb+1], a0, a1, a2, a3, vh2, vh3);
            }
        }
    }

    float inv0 = 1.f / l0;
    float inv1 = 1.f / l1;
    int row0g = q0 + warp * 16 + g;
    int row1g = row0g + 8;
    __half* Ohb = Oh + (size_t)(b * SS) * DD + h * HD;
    #pragma unroll
    for (int nb = 0; nb < 8; nb++) {
        int col = nb * 8 + 2 * t;
        *(uint32_t*)(Ohb + (size_t)row0g * DD + col) =
            pack_h2(o[nb][0] * inv0, o[nb][1] * inv0);
        *(uint32_t*)(Ohb + (size_t)row1g * DD + col) =
            pack_h2(o[nb][2] * inv1, o[nb][3] * inv1);
    }
}

// ---------------- fused residual + LayerNorm --------------------------------
template<int SPLIT>
__global__ __launch_bounds__(256)
void ln_kernel(const float* __restrict__ A,
               const float* __restrict__ R,
               const float* __restrict__ g,
               const float* __restrict__ be,
               float* __restrict__ out,
               __half* __restrict__ oh)
{
    int row = blockIdx.x;
    int t   = threadIdx.x;
    const float4* a4 = (const float4*)(A + (size_t)row * DD);
    const float4* r4 = (const float4*)(R + (size_t)row * DD);
    float4 av = a4[t];
    float4 rv = r4[t];
    float x0 = av.x + rv.x, x1 = av.y + rv.y, x2 = av.z + rv.z, x3 = av.w + rv.w;

    float s = x0 + x1 + x2 + x3;
    float q = x0 * x0 + x1 * x1 + x2 * x2 + x3 * x3;
    #pragma unroll
    for (int off = 16; off >= 1; off >>= 1) {
        s += __shfl_xor_sync(0xffffffffu, s, off);
        q += __shfl_xor_sync(0xffffffffu, q, off);
    }
    __shared__ float rs[8], rq[8];
    int w = t >> 5, lane = t & 31;
    if (lane == 0) { rs[w] = s; rq[w] = q; }
    __syncthreads();
    float tot = 0.f, totq = 0.f;
    #pragma unroll
    for (int i = 0; i < 8; i++) { tot += rs[i]; totq += rq[i]; }

    float mean = tot * (1.f / DD);
    float var  = totq * (1.f / DD) - mean * mean;
    float rstd = rsqrtf(var + EPSL);

    float4 gv = ((const float4*)g)[t];
    float4 bv = ((const float4*)be)[t];
    float4 ov;
    ov.x = (x0 - mean) * rstd * gv.x + bv.x;
    ov.y = (x1 - mean) * rstd * gv.y + bv.y;
    ov.z = (x2 - mean) * rstd * gv.z + bv.z;
    ov.w = (x3 - mean) * rstd * gv.w + bv.w;
    ((float4*)(out + (size_t)row * DD))[t] = ov;

    if (SPLIT) {
        uint2 uh;
        __half* hp = (__half*)&uh;
        hp[0] = __float2half_rn(ov.x);
        hp[1] = __float2half_rn(ov.y);
        hp[2] = __float2half_rn(ov.z);
        hp[3] = __float2half_rn(ov.w);
        ((uint2*)(oh + (size_t)row * DD))[t] = uh;
    }
}

// ---------------- launch ----------------------------------------------------
extern "C" void kernel_launch(void* const* d_in, const int* in_sizes, int n_in,
                              void* d_out, int out_size)
{
    const float* x   = (const float*)d_in[0];
    const int*   vl  = (const int*)  d_in[1];
    const float* Wq  = (const float*)d_in[2];
    const float* Wk  = (const float*)d_in[3];
    const float* Wv  = (const float*)d_in[4];
    const float* Wo  = (const float*)d_in[5];
    const float* W1  = (const float*)d_in[6];
    const float* b1  = (const float*)d_in[7];
    const float* W2  = (const float*)d_in[8];
    const float* b2  = (const float*)d_in[9];
    const float* g1  = (const float*)d_in[10];
    const float* be1 = (const float*)d_in[11];
    const float* g2  = (const float*)d_in[12];
    const float* be2 = (const float*)d_in[13];
    float* out = (float*)d_out;

    float *q, *k, *r;
    cudaGetSymbolAddress((void**)&q, g_q);
    cudaGetSymbolAddress((void**)&k, g_k);
    cudaGetSymbolAddress((void**)&r, g_r);

    __half *xh, *qkv, *ah, *rh, *ffh;
    cudaGetSymbolAddress((void**)&xh,  g_xh);
    cudaGetSymbolAddress((void**)&qkv, g_qkv);
    cudaGetSymbolAddress((void**)&ah,  g_ah);
    cudaGetSymbolAddress((void**)&rh,  g_rh);
    cudaGetSymbolAddress((void**)&ffh, g_ffh);

    __half *wqkv, *wo, *w1, *w2;
    cudaGetSymbolAddress((void**)&wqkv, g_wqkv);
    cudaGetSymbolAddress((void**)&wo, g_wo);
    cudaGetSymbolAddress((void**)&w1, g_w1);
    cudaGetSymbolAddress((void**)&w2, g_w2);

    int gemm_smem = NST * STG4;   // 81408
    cudaFuncSetAttribute(hgemm4_kernel<0>, cudaFuncAttributeMaxDynamicSharedMemorySize, gemm_smem);
    cudaFuncSetAttribute(hgemm4_kernel<1>, cudaFuncAttributeMaxDynamicSharedMemorySize, gemm_smem);
    cudaFuncSetAttribute(hgemm4_kernel<2>, cudaFuncAttributeMaxDynamicSharedMemorySize, gemm_smem);
    cudaFuncSetAttribute(hgemm4_kernel<3>, cudaFuncAttributeMaxDynamicSharedMemorySize, gemm_smem);

    // one-shot fp16 conversion of weights + input
    SplitArgs sa;
    sa.s[0] = {Wq, wqkv, DD*DD/1024, DD, 3*DD, 0};
    sa.s[1] = {Wk, wqkv, DD*DD/1024, DD, 3*DD, DD};
    sa.s[2] = {Wv, wqkv, DD*DD/1024, DD, 3*DD, 2*DD};
    sa.s[3] = {Wo, wo,   DD*DD/1024, DD, DD,  0};
    sa.s[4] = {W1, w1,   DD*FF/1024, FF, FF,  0};
    sa.s[5] = {W2, w2,   DD*FF/1024, DD, DD,  0};
    sa.s[6] = {x,  xh,   NR*DD/1024, DD, DD,  0};
    int nblk = 0;
    for (int i = 0; i < 7; i++) nblk += sa.s[i].nblk;
    split_all_kernel<<<nblk, 256>>>(sa);

    dim3 gQKV(3 * DD / 256, NR / 128);   // (12, 64)
    dim3 gD(DD / 256, NR / 128);         // (4, 64)
    dim3 gF(FF / 256, NR / 128);         // (16, 64)

    // fused QKV projection -> fp16 [NR, 3*DD]
    hgemm4_kernel<3><<<gQKV, 256, gemm_smem>>>(NR, 3 * DD, DD, xh, wqkv,
                                               nullptr, nullptr, qkv);

    // attention -> fp16 [NR, DD]
    attn_f16_kernel<<<dim3(SS / 64, BB * HH), 128>>>(qkv, vl, ah);

    // output projection -> q fp32
    hgemm4_kernel<0><<<gD, 256, gemm_smem>>>(NR, DD, DD, ah, wo,
                                             nullptr, q, nullptr);

    // residual + LN1 -> r fp32 + rh fp16
    ln_kernel<1><<<NR, 256>>>(q, x, g1, be1, r, rh);

    // FFN
    hgemm4_kernel<1><<<gF, 256, gemm_smem>>>(NR, FF, DD, rh, w1, b1, nullptr, ffh);
    hgemm4_kernel<2><<<gD, 256, gemm_smem>>>(NR, DD, FF, ffh, w2, b2, k, nullptr);

    // residual + LN2 -> output
    ln_kernel<0><<<NR, 256>>>(k, r, g2, be2, out, nullptr);
}

// round 11
// speedup vs baseline: 1.0010x; 1.0010x over previous
#include <cuda_runtime.h>
#include <cuda_fp16.h>
#include <math.h>
#include <stdint.h>

// Problem constants
#define BB   4
#define SS   2048
#define DD   1024
#define HH   16
#define HD   64
#define FF   4096
#define NR   (BB*SS)          // 8192 rows
#define EPSL 1e-5f

// ---------------- scratch (device globals; no allocation allowed) ----------
__device__ float g_q [NR*DD];        // Wo output fp32
__device__ float g_k [NR*DD];        // FF2 output fp32
__device__ float g_r [NR*DD];        // LN1 output fp32

// fp16 activations (single term)
__device__ __align__(16) __half g_xh  [NR*DD];
__device__ __align__(16) __half g_qkv [(size_t)NR*3*DD];   // fused QKV output
__device__ __align__(16) __half g_ah  [NR*DD];
__device__ __align__(16) __half g_rh  [NR*DD];
__device__ __align__(16) __half g_ffh [(size_t)NR*FF];

// fp16 weights. QKV concatenated along N: [DD, 3*DD]
__device__ __align__(16) __half g_wqkv[DD*3*DD];
__device__ __align__(16) __half g_wo  [DD*DD];
__device__ __align__(16) __half g_w1  [(size_t)DD*FF];
__device__ __align__(16) __half g_w2  [(size_t)DD*FF];

// ---------------- asm helpers ------------------------------------------------
#define LDSM_X4(R0,R1,R2,R3,ADDR) \
    asm volatile("ldmatrix.sync.aligned.m8n8.x4.shared.b16 {%0,%1,%2,%3},[%4];" \
        : "=r"(R0),"=r"(R1),"=r"(R2),"=r"(R3) : "r"(ADDR))

#define LDSM_X4_T(R0,R1,R2,R3,ADDR) \
    asm volatile("ldmatrix.sync.aligned.m8n8.x4.trans.shared.b16 {%0,%1,%2,%3},[%4];" \
        : "=r"(R0),"=r"(R1),"=r"(R2),"=r"(R3) : "r"(ADDR))

#define MMAH(D,A0,A1,A2,A3,B0,B1) \
    asm volatile("mma.sync.aligned.m16n8k16.row.col.f32.f16.f16.f32 " \
        "{%0,%1,%2,%3},{%4,%5,%6,%7},{%8,%9},{%0,%1,%2,%3};" \
        : "+f"(D[0]),"+f"(D[1]),"+f"(D[2]),"+f"(D[3]) \
        : "r"(A0),"r"(A1),"r"(A2),"r"(A3),"r"(B0),"r"(B1))

__device__ __forceinline__ void cp16(uint32_t dst, const void* src) {
    asm volatile("cp.async.cg.shared.global [%0],[%1],16;" :: "r"(dst), "l"(src));
}
#define CP_COMMIT() asm volatile("cp.async.commit_group;" ::: "memory")
#define CP_WAIT0()  asm volatile("cp.async.wait_group 0;" ::: "memory")
#define CP_WAIT1()  asm volatile("cp.async.wait_group 1;" ::: "memory")

__device__ __forceinline__ uint32_t pack_h2(float a, float b) {
    __half2 h = __floats2half2_rn(a, b);
    return *reinterpret_cast<uint32_t*>(&h);
}

// fast exp on the FMA pipe. x <= 0 expected. ~2e-6 rel err.
__device__ __forceinline__ float expf_fast(float x) {
    float y = fmaxf(x * 1.44269504088896f, -126.f);
    float fl = floorf(y);
    float f = y - fl;
    float p = 1.54653240e-4f;
    p = fmaf(p, f, 1.33335581e-3f);
    p = fmaf(p, f, 9.61812910e-3f);
    p = fmaf(p, f, 5.55041086e-2f);
    p = fmaf(p, f, 2.40226507e-1f);
    p = fmaf(p, f, 6.93147181e-1f);
    p = fmaf(p, f, 1.0f);
    int ei = (int)fl;
    float sc = __int_as_float((ei + 127) << 23);
    return p * sc;
}

// ---------------- one-shot fp32 -> fp16 convert, all tensors -----------------
struct SplitSeg {
    const float* src;
    __half* h;
    int nblk;         // blocks of 1024 elems
    int cols;         // source row length
    int stride;       // dst row stride
    int off;          // dst column offset
};
struct SplitArgs { SplitSeg s[7]; };

__global__ __launch_bounds__(256)
void split_all_kernel(SplitArgs a)
{
    int blk = blockIdx.x;
    int i = 0;
    while (blk >= a.s[i].nblk) { blk -= a.s[i].nblk; i++; }
    SplitSeg sg = a.s[i];

    int e   = blk * 1024 + threadIdx.x * 4;
    int row = e / sg.cols;
    int col = e - row * sg.cols;
    size_t d = (size_t)row * sg.stride + sg.off + col;

    float4 v = *(const float4*)(sg.src + (size_t)e);
    float av[4] = {v.x, v.y, v.z, v.w};
    uint2 uh;
    __half* hp = (__half*)&uh;
    #pragma unroll
    for (int j = 0; j < 4; j++) hp[j] = __float2half_rn(av[j]);
    *(uint2*)(sg.h + d) = uh;
}

// ---------------- HMMA GEMM: BM=128, BN=256, warp tile 64x64 -----------------
// C[M,N] = A[M,K] @ B[K,N], fp16 in, fp32 accum. 256 threads, 8 warps (2x4).
// stage: A 128x32 @pitch80 = 10240 B, B 32x256 @pitch528 = 16896 B -> 27136 B.
// 3 stages = 81408 B, 1 CTA/SM. Pitches mod 128 = {80,16}: ldmatrix
// conflict-free (8 row-phases distinct).
#define PAB 80
#define PBB 528
#define STG4 27136
#define NST 3

__device__ __forceinline__ void load_stage(
    uint32_t sb,
    const __half* __restrict__ Ah,
    const __half* __restrict__ Bh, int K, int N, int tid)
{
    // A: 512 chunks
    #pragma unroll
    for (int it = 0; it < 2; it++) {
        int idx = it * 256 + tid;
        int r = idx >> 2, c4 = idx & 3;
        cp16(sb + r * PAB + c4 * 16, Ah + (size_t)r * K + c4 * 8);
    }
    // B: 1024 chunks (32 rows x 32 chunks)
    #pragma unroll
    for (int it = 0; it < 4; it++) {
        int idx = it * 256 + tid;
        int r = idx >> 5, c16 = idx & 31;
        cp16(sb + 10240 + r * PBB + c16 * 16, Bh + (size_t)r * N + c16 * 8);
    }
}

// EPI: 0 plain fp32 | 1 bias+relu -> fp16 | 2 bias -> fp32 | 3 plain -> fp16
template<int EPI>
__global__ __launch_bounds__(256)
void hgemm4_kernel(int M, int N, int K,
                   const __half* __restrict__ Ah,
                   const __half* __restrict__ Bh,
                   const float* __restrict__ bias,
                   float* __restrict__ C,
                   __half* __restrict__ Ch)
{
    extern __shared__ __align__(16) char smem[];
    uint32_t sb = (uint32_t)__cvta_generic_to_shared(smem);

    int tid  = threadIdx.x;
    int lane = tid & 31;
    int warp = tid >> 5;
    int wm = warp & 1;            // 2 warps along M -> 64 rows each
    int wn = warp >> 1;           // 4 warps along N -> 64 cols each
    int row0 = blockIdx.y * 128;
    int col0 = blockIdx.x * 256;

    const __half* Ahb = Ah + (size_t)row0 * K;
    const __half* Bhb = Bh + col0;

    float acc[4][8][4];
    #pragma unroll
    for (int i = 0; i < 4; i++)
        #pragma unroll
        for (int j = 0; j < 8; j++)
            #pragma unroll
            for (int c = 0; c < 4; c++) acc[i][j][c] = 0.f;

    int NT = K / 32;

    #pragma unroll
    for (int i = 0; i < NST - 1; i++) {
        load_stage(sb + i * STG4, Ahb + i * 32, Bhb + (size_t)(i * 32) * N, K, N, tid);
        CP_COMMIT();
    }

    for (int kt = 0; kt < NT; kt++) {
        CP_WAIT1();
        __syncthreads();

        int nk = kt + NST - 1;
        if (nk < NT) {
            load_stage(sb + (nk % NST) * STG4, Ahb + nk * 32,
                       Bhb + (size_t)(nk * 32) * N, K, N, tid);
        }
        CP_COMMIT();

        uint32_t st = sb + (kt % NST) * STG4;
        #pragma unroll
        for (int kk = 0; kk < 32; kk += 16) {
            uint32_t ahi[4][4], bfr[8][2];

            #pragma unroll
            for (int mi = 0; mi < 4; mi++) {
                int r = wm * 64 + mi * 16 + (lane & 15);
                int c = kk + (lane >> 4) * 8;
                LDSM_X4(ahi[mi][0], ahi[mi][1], ahi[mi][2], ahi[mi][3], st + r * PAB + c * 2);
            }
            #pragma unroll
            for (int cb = 0; cb < 4; cb++) {
                int r = kk + (lane & 15);
                int c = wn * 64 + cb * 16 + (lane >> 4) * 8;
                uint32_t bh = st + 10240 + r * PBB + c * 2;
                LDSM_X4_T(bfr[cb*2][0], bfr[cb*2][1], bfr[cb*2+1][0], bfr[cb*2+1][1], bh);
            }

            #pragma unroll
            for (int mi = 0; mi < 4; mi++)
                #pragma unroll
                for (int ni = 0; ni < 8; ni++)
                    MMAH(acc[mi][ni], ahi[mi][0], ahi[mi][1], ahi[mi][2], ahi[mi][3],
                         bfr[ni][0], bfr[ni][1]);
        }
    }

    // epilogue
    int g = lane >> 2, t = lane & 3;
    #pragma unroll
    for (int mi = 0; mi < 4; mi++) {
        #pragma unroll
        for (int ni = 0; ni < 8; ni++) {
            int r = row0 + wm * 64 + mi * 16 + g;
            int c = col0 + wn * 64 + ni * 8 + t * 2;
            float v0 = acc[mi][ni][0], v1 = acc[mi][ni][1];
            float v2 = acc[mi][ni][2], v3 = acc[mi][ni][3];

            if (EPI == 1 || EPI == 2) {
                float bz0 = bias[c], bz1 = bias[c + 1];
                v0 += bz0; v1 += bz1; v2 += bz0; v3 += bz1;
            }
            if (EPI == 1) {
                v0 = fmaxf(v0, 0.f); v1 = fmaxf(v1, 0.f);
                v2 = fmaxf(v2, 0.f); v3 = fmaxf(v3, 0.f);
            }

            if (EPI == 0 || EPI == 2) {
                *(float2*)&C[(size_t)r * N + c]       = make_float2(v0, v1);
                *(float2*)&C[(size_t)(r + 8) * N + c] = make_float2(v2, v3);
            } else {
                *(uint32_t*)&Ch[(size_t)r * N + c]       = pack_h2(v0, v1);
                *(uint32_t*)&Ch[(size_t)(r + 8) * N + c] = pack_h2(v2, v3);
            }
        }
    }
}

// ---------------- flash attention: fp16 single-term, cp.async ----------------
// QKV input fused layout [NR, 3*DD]; Q at col 0, K at DD, V at 2*DD.
#define QKVS (3*DD)

__device__ __forceinline__ void load_kv(uint32_t buf,
                                        const __half* __restrict__ KhB,
                                        const __half* __restrict__ VhB,
                                        int k0, int tid)
{
    #pragma unroll
    for (int it = 0; it < 4; it++) {
        int idx = it * 128 + tid;
        int r = idx >> 3, c = idx & 7;
        cp16(buf + r * 144 + c * 16,        KhB + (size_t)(k0 + r) * QKVS + c * 8);
        cp16(buf + 9216 + r * 144 + c * 16, VhB + (size_t)(k0 + r) * QKVS + c * 8);
    }
}

__global__ __launch_bounds__(128)
void attn_f16_kernel(const __half* __restrict__ QKV,
                     const int* __restrict__ vlen,
                     __half* __restrict__ Oh)
{
    __shared__ __align__(16) char smem[36864];
    uint32_t sb = (uint32_t)__cvta_generic_to_shared(smem);

    int tid  = threadIdx.x;
    int lane = tid & 31;
    int warp = tid >> 5;
    int g    = lane >> 2;
    int t    = lane & 3;

    int bh = blockIdx.y;
    int b  = bh >> 4;
    int h  = bh & 15;
    int q0 = blockIdx.x * 64;
    int vl = vlen[b];

    size_t base = (size_t)(b * SS) * QKVS + h * HD;
    const __half* QhB = QKV + base + (size_t)q0 * QKVS;
    const __half* KhB = QKV + base + DD;
    const __half* VhB = QKV + base + 2 * DD;

    // stage Q
    #pragma unroll
    for (int it = 0; it < 4; it++) {
        int idx = it * 128 + tid;
        int r = idx >> 3, c = idx & 7;
        cp16(sb + r * 144 + c * 16, QhB + (size_t)r * QKVS + c * 8);
    }
    CP_COMMIT(); CP_WAIT0();
    __syncthreads();

    uint32_t qh[4][4];
    #pragma unroll
    for (int kk = 0; kk < 4; kk++) {
        int r = warp * 16 + (lane & 15);
        int c = kk * 16 + (lane >> 4) * 8;
        LDSM_X4(qh[kk][0], qh[kk][1], qh[kk][2], qh[kk][3], sb + r * 144 + c * 2);
    }
    __syncthreads();

    float o[8][4];
    #pragma unroll
    for (int i = 0; i < 8; i++)
        #pragma unroll
        for (int c = 0; c < 4; c++) o[i][c] = 0.f;
    float m0 = -1e30f, m1 = -1e30f, l0 = 0.f, l1 = 0.f;

    int nkt = (vl + 63) >> 6;

    load_kv(sb, KhB, VhB, 0, tid);
    CP_COMMIT();

    for (int kt = 0; kt < nkt; kt++) {
        __syncthreads();
        if (kt + 1 < nkt)
            load_kv(sb + ((kt + 1) & 1) * 18432, KhB, VhB, (kt + 1) * 64, tid);
        CP_COMMIT();
        CP_WAIT1();
        __syncthreads();

        uint32_t cur = sb + (kt & 1) * 18432;
        int k0 = kt * 64;

        float s[8][4];
        #pragma unroll
        for (int i = 0; i < 8; i++)
            #pragma unroll
            for (int c = 0; c < 4; c++) s[i][c] = 0.f;

        #pragma unroll
        for (int kk = 0; kk < 4; kk++) {
            #pragma unroll
            for (int nb = 0; nb < 4; nb++) {
                int r = nb * 16 + (lane & 15);
                int c = kk * 16 + (lane >> 4) * 8;
                uint32_t kh0, kh1, kh2, kh3;
                LDSM_X4(kh0, kh1, kh2, kh3, cur + r * 144 + c * 2);
                MMAH(s[2*nb],   qh[kk][0], qh[kk][1], qh[kk][2], qh[kk][3], kh0, kh2);
                MMAH(s[2*nb+1], qh[kk][0], qh[kk][1], qh[kk][2], qh[kk][3], kh1, kh3);
            }
        }

        #pragma unroll
        for (int nb = 0; nb < 8; nb++) {
            int c0 = k0 + nb * 8 + 2 * t;
            int c1 = c0 + 1;
            s[nb][0] = (c0 < vl) ? s[nb][0] * 0.125f : -1e30f;
            s[nb][1] = (c1 < vl) ? s[nb][1] * 0.125f : -1e30f;
            s[nb][2] = (c0 < vl) ? s[nb][2] * 0.125f : -1e30f;
            s[nb][3] = (c1 < vl) ? s[nb][3] * 0.125f : -1e30f;
        }

        float tm0 = -1e30f, tm1 = -1e30f;
        #pragma unroll
        for (int nb = 0; nb < 8; nb++) {
            tm0 = fmaxf(tm0, fmaxf(s[nb][0], s[nb][1]));
            tm1 = fmaxf(tm1, fmaxf(s[nb][2], s[nb][3]));
        }
        tm0 = fmaxf(tm0, __shfl_xor_sync(0xffffffffu, tm0, 1));
        tm0 = fmaxf(tm0, __shfl_xor_sync(0xffffffffu, tm0, 2));
        tm1 = fmaxf(tm1, __shfl_xor_sync(0xffffffffu, tm1, 1));
        tm1 = fmaxf(tm1, __shfl_xor_sync(0xffffffffu, tm1, 2));

        float mn0 = fmaxf(m0, tm0);
        float mn1 = fmaxf(m1, tm1);
        float al0 = expf_fast(m0 - mn0);
        float al1 = expf_fast(m1 - mn1);

        uint32_t pA[4][4];
        float ls0 = 0.f, ls1 = 0.f;
        #pragma unroll
        for (int nb = 0; nb < 8; nb++) {
            float p0 = expf_fast(s[nb][0] - mn0);
            float p1 = expf_fast(s[nb][1] - mn0);
            float p2 = expf_fast(s[nb][2] - mn1);
            float p3 = expf_fast(s[nb][3] - mn1);
            ls0 += p0 + p1;
            ls1 += p2 + p3;
            int ks = nb >> 1;
            int hf = (nb & 1) * 2;
            pA[ks][hf + 0] = pack_h2(p0, p1);
            pA[ks][hf + 1] = pack_h2(p2, p3);
        }
        ls0 += __shfl_xor_sync(0xffffffffu, ls0, 1);
        ls0 += __shfl_xor_sync(0xffffffffu, ls0, 2);
        ls1 += __shfl_xor_sync(0xffffffffu, ls1, 1);
        ls1 += __shfl_xor_sync(0xffffffffu, ls1, 2);

        l0 = l0 * al0 + ls0;
        l1 = l1 * al1 + ls1;
        m0 = mn0;
        m1 = mn1;

        #pragma unroll
        for (int nb = 0; nb < 8; nb++) {
            o[nb][0] *= al0; o[nb][1] *= al0;
            o[nb][2] *= al1; o[nb][3] *= al1;
        }

        #pragma unroll
        for (int kk = 0; kk < 4; kk++) {
            uint32_t a0 = pA[kk][0], a1 = pA[kk][1], a2 = pA[kk][2], a3 = pA[kk][3];
            #pragma unroll
            for (int nb = 0; nb < 4; nb++) {
                int r = kk * 16 + (lane & 15);
                int c = nb * 16 + (lane >> 4) * 8;
                uint32_t vh0, vh1, vh2, vh3;
                LDSM_X4_T(vh0, vh1, vh2, vh3, cur + 9216 + r * 144 + c * 2);
                MMAH(o[2*nb],   a0, a1, a2, a3, vh0, vh1);
                MMAH(o[2*nb+1], a0, a1, a2, a3, vh2, vh3);
            }
        }
    }

    float inv0 = 1.f / l0;
    float inv1 = 1.f / l1;
    int row0g = q0 + warp * 16 + g;
    int row1g = row0g + 8;
    __half* Ohb = Oh + (size_t)(b * SS) * DD + h * HD;
    #pragma unroll
    for (int nb = 0; nb < 8; nb++) {
        int col = nb * 8 + 2 * t;
        *(uint32_t*)(Ohb + (size_t)row0g * DD + col) =
            pack_h2(o[nb][0] * inv0, o[nb][1] * inv0);
        *(uint32_t*)(Ohb + (size_t)row1g * DD + col) =
            pack_h2(o[nb][2] * inv1, o[nb][3] * inv1);
    }
}

// ---------------- fused residual + LayerNorm --------------------------------
template<int SPLIT>
__global__ __launch_bounds__(256)
void ln_kernel(const float* __restrict__ A,
               const float* __restrict__ R,
               const float* __restrict__ g,
               const float* __restrict__ be,
               float* __restrict__ out,
               __half* __restrict__ oh)
{
    int row = blockIdx.x;
    int t   = threadIdx.x;
    const float4* a4 = (const float4*)(A + (size_t)row * DD);
    const float4* r4 = (const float4*)(R + (size_t)row * DD);
    float4 av = a4[t];
    float4 rv = r4[t];
    float x0 = av.x + rv.x, x1 = av.y + rv.y, x2 = av.z + rv.z, x3 = av.w + rv.w;

    float s = x0 + x1 + x2 + x3;
    float q = x0 * x0 + x1 * x1 + x2 * x2 + x3 * x3;
    #pragma unroll
    for (int off = 16; off >= 1; off >>= 1) {
        s += __shfl_xor_sync(0xffffffffu, s, off);
        q += __shfl_xor_sync(0xffffffffu, q, off);
    }
    __shared__ float rs[8], rq[8];
    int w = t >> 5, lane = t & 31;
    if (lane == 0) { rs[w] = s; rq[w] = q; }
    __syncthreads();
    float tot = 0.f, totq = 0.f;
    #pragma unroll
    for (int i = 0; i < 8; i++) { tot += rs[i]; totq += rq[i]; }

    float mean = tot * (1.f / DD);
    float var  = totq * (1.f / DD) - mean * mean;
    float rstd = rsqrtf(var + EPSL);

    float4 gv = ((const float4*)g)[t];
    float4 bv = ((const float4*)be)[t];
    float4 ov;
    ov.x = (x0 - mean) * rstd * gv.x + bv.x;
    ov.y = (x1 - mean) * rstd * gv.y + bv.y;
    ov.z = (x2 - mean) * rstd * gv.z + bv.z;
    ov.w = (x3 - mean) * rstd * gv.w + bv.w;
    ((float4*)(out + (size_t)row * DD))[t] = ov;

    if (SPLIT) {
        uint2 uh;
        __half* hp = (__half*)&uh;
        hp[0] = __float2half_rn(ov.x);
        hp[1] = __float2half_rn(ov.y);
        hp[2] = __float2half_rn(ov.z);
        hp[3] = __float2half_rn(ov.w);
        ((uint2*)(oh + (size_t)row * DD))[t] = uh;
    }
}

// ---------------- launch ----------------------------------------------------
extern "C" void kernel_launch(void* const* d_in, const int* in_sizes, int n_in,
                              void* d_out, int out_size)
{
    const float* x   = (const float*)d_in[0];
    const int*   vl  = (const int*)  d_in[1];
    const float* Wq  = (const float*)d_in[2];
    const float* Wk  = (const float*)d_in[3];
    const float* Wv  = (const float*)d_in[4];
    const float* Wo  = (const float*)d_in[5];
    const float* W1  = (const float*)d_in[6];
    const float* b1  = (const float*)d_in[7];
    const float* W2  = (const float*)d_in[8];
    const float* b2  = (const float*)d_in[9];
    const float* g1  = (const float*)d_in[10];
    const float* be1 = (const float*)d_in[11];
    const float* g2  = (const float*)d_in[12];
    const float* be2 = (const float*)d_in[13];
    float* out = (float*)d_out;

    float *q, *k, *r;
    cudaGetSymbolAddress((void**)&q, g_q);
    cudaGetSymbolAddress((void**)&k, g_k);
    cudaGetSymbolAddress((void**)&r, g_r);

    __half *xh, *qkv, *ah, *rh, *ffh;
    cudaGetSymbolAddress((void**)&xh,  g_xh);
    cudaGetSymbolAddress((void**)&qkv, g_qkv);
    cudaGetSymbolAddress((void**)&ah,  g_ah);
    cudaGetSymbolAddress((void**)&rh,  g_rh);
    cudaGetSymbolAddress((void**)&ffh, g_ffh);

    __half *wqkv, *wo, *w1, *w2;
    cudaGetSymbolAddress((void**)&wqkv, g_wqkv);
    cudaGetSymbolAddress((void**)&wo, g_wo);
    cudaGetSymbolAddress((void**)&w1, g_w1);
    cudaGetSymbolAddress((void**)&w2, g_w2);

    int gemm_smem = NST * STG4;   // 81408
    cudaFuncSetAttribute(hgemm4_kernel<0>, cudaFuncAttributeMaxDynamicSharedMemorySize, gemm_smem);
    cudaFuncSetAttribute(hgemm4_kernel<1>, cudaFuncAttributeMaxDynamicSharedMemorySize, gemm_smem);
    cudaFuncSetAttribute(hgemm4_kernel<2>, cudaFuncAttributeMaxDynamicSharedMemorySize, gemm_smem);
    cudaFuncSetAttribute(hgemm4_kernel<3>, cudaFuncAttributeMaxDynamicSharedMemorySize, gemm_smem);

    // one-shot fp16 conversion of weights + input
    SplitArgs sa;
    sa.s[0] = {Wq, wqkv, DD*DD/1024, DD, 3*DD, 0};
    sa.s[1] = {Wk, wqkv, DD*DD/1024, DD, 3*DD, DD};
    sa.s[2] = {Wv, wqkv, DD*DD/1024, DD, 3*DD, 2*DD};
    sa.s[3] = {Wo, wo,   DD*DD/1024, DD, DD,  0};
    sa.s[4] = {W1, w1,   DD*FF/1024, FF, FF,  0};
    sa.s[5] = {W2, w2,   DD*FF/1024, DD, DD,  0};
    sa.s[6] = {x,  xh,   NR*DD/1024, DD, DD,  0};
    int nblk = 0;
    for (int i = 0; i < 7; i++) nblk += sa.s[i].nblk;
    split_all_kernel<<<nblk, 256>>>(sa);

    dim3 gQKV(3 * DD / 256, NR / 128);   // (12, 64)
    dim3 gD(DD / 256, NR / 128);         // (4, 64)
    dim3 gF(FF / 256, NR / 128);         // (16, 64)

    // fused QKV projection -> fp16 [NR, 3*DD]
    hgemm4_kernel<3><<<gQKV, 256, gemm_smem>>>(NR, 3 * DD, DD, xh, wqkv,
                                               nullptr, nullptr, qkv);

    // attention -> fp16 [NR, DD]
    attn_f16_kernel<<<dim3(SS / 64, BB * HH), 128>>>(qkv, vl, ah);

    // output projection -> q fp32
    hgemm4_kernel<0><<<gD, 256, gemm_smem>>>(NR, DD, DD, ah, wo,
                                             nullptr, q, nullptr);

    // residual + LN1 -> r fp32 + rh fp16
    ln_kernel<1><<<NR, 256>>>(q, x, g1, be1, r, rh);

    // FFN
    hgemm4_kernel<1><<<gF, 256, gemm_smem>>>(NR, FF, DD, rh, w1, b1, nullptr, ffh);
    hgemm4_kernel<2><<<gD, 256, gemm_smem>>>(NR, DD, FF, ffh, w2, b2, k, nullptr);

    // residual + LN2 -> output
    ln_kernel<0><<<NR, 256>>>(k, r, g2, be2, out, nullptr);
}

// round 12
// speedup vs baseline: 1.1056x; 1.1045x over previous
#include <cuda_runtime.h>
#include <cuda_fp16.h>
#include <math.h>
#include <stdint.h>

// Problem constants
#define BB   4
#define SS   2048
#define DD   1024
#define HH   16
#define HD   64
#define FF   4096
#define NR   (BB*SS)          // 8192 rows
#define EPSL 1e-5f

// ---------------- scratch (device globals; no allocation allowed) ----------
__device__ float g_q [NR*DD];        // Wo output fp32
__device__ float g_k [NR*DD];        // FF2 output fp32
__device__ float g_r [NR*DD];        // LN1 output fp32

// fp16 activations (single term)
__device__ __align__(16) __half g_xh  [NR*DD];
__device__ __align__(16) __half g_qkv [(size_t)NR*3*DD];   // fused QKV output
__device__ __align__(16) __half g_ah  [NR*DD];
__device__ __align__(16) __half g_rh  [NR*DD];
__device__ __align__(16) __half g_ffh [(size_t)NR*FF];

// fp16 weights. QKV concatenated along N: [DD, 3*DD]
__device__ __align__(16) __half g_wqkv[DD*3*DD];
__device__ __align__(16) __half g_wo  [DD*DD];
__device__ __align__(16) __half g_w1  [(size_t)DD*FF];
__device__ __align__(16) __half g_w2  [(size_t)DD*FF];

// ---------------- asm helpers ------------------------------------------------
#define LDSM_X4(R0,R1,R2,R3,ADDR) \
    asm volatile("ldmatrix.sync.aligned.m8n8.x4.shared.b16 {%0,%1,%2,%3},[%4];" \
        : "=r"(R0),"=r"(R1),"=r"(R2),"=r"(R3) : "r"(ADDR))

#define LDSM_X4_T(R0,R1,R2,R3,ADDR) \
    asm volatile("ldmatrix.sync.aligned.m8n8.x4.trans.shared.b16 {%0,%1,%2,%3},[%4];" \
        : "=r"(R0),"=r"(R1),"=r"(R2),"=r"(R3) : "r"(ADDR))

#define MMAH(D,A0,A1,A2,A3,B0,B1) \
    asm volatile("mma.sync.aligned.m16n8k16.row.col.f32.f16.f16.f32 " \
        "{%0,%1,%2,%3},{%4,%5,%6,%7},{%8,%9},{%0,%1,%2,%3};" \
        : "+f"(D[0]),"+f"(D[1]),"+f"(D[2]),"+f"(D[3]) \
        : "r"(A0),"r"(A1),"r"(A2),"r"(A3),"r"(B0),"r"(B1))

__device__ __forceinline__ void cp16(uint32_t dst, const void* src) {
    asm volatile("cp.async.cg.shared.global [%0],[%1],16;" :: "r"(dst), "l"(src));
}
#define CP_COMMIT() asm volatile("cp.async.commit_group;" ::: "memory")
#define CP_WAIT0()  asm volatile("cp.async.wait_group 0;" ::: "memory")
#define CP_WAIT1()  asm volatile("cp.async.wait_group 1;" ::: "memory")

__device__ __forceinline__ uint32_t pack_h2(float a, float b) {
    __half2 h = __floats2half2_rn(a, b);
    return *reinterpret_cast<uint32_t*>(&h);
}

// fast exp on the FMA pipe. x <= 0 expected. ~2e-6 rel err.
__device__ __forceinline__ float expf_fast(float x) {
    float y = fmaxf(x * 1.44269504088896f, -126.f);
    float fl = floorf(y);
    float f = y - fl;
    float p = 1.54653240e-4f;
    p = fmaf(p, f, 1.33335581e-3f);
    p = fmaf(p, f, 9.61812910e-3f);
    p = fmaf(p, f, 5.55041086e-2f);
    p = fmaf(p, f, 2.40226507e-1f);
    p = fmaf(p, f, 6.93147181e-1f);
    p = fmaf(p, f, 1.0f);
    int ei = (int)fl;
    float sc = __int_as_float((ei + 127) << 23);
    return p * sc;
}

// ---------------- one-shot fp32 -> fp16 convert, all tensors -----------------
struct SplitSeg {
    const float* src;
    __half* h;
    int nblk;         // blocks of 1024 elems
    int cols;         // source row length
    int stride;       // dst row stride
    int off;          // dst column offset
};
struct SplitArgs { SplitSeg s[7]; };

__global__ __launch_bounds__(256)
void split_all_kernel(SplitArgs a)
{
    int blk = blockIdx.x;
    int i = 0;
    while (blk >= a.s[i].nblk) { blk -= a.s[i].nblk; i++; }
    SplitSeg sg = a.s[i];

    int e   = blk * 1024 + threadIdx.x * 4;
    int row = e / sg.cols;
    int col = e - row * sg.cols;
    size_t d = (size_t)row * sg.stride + sg.off + col;

    float4 v = *(const float4*)(sg.src + (size_t)e);
    float av[4] = {v.x, v.y, v.z, v.w};
    uint2 uh;
    __half* hp = (__half*)&uh;
    #pragma unroll
    for (int j = 0; j < 4; j++) hp[j] = __float2half_rn(av[j]);
    *(uint2*)(sg.h + d) = uh;
}

// ---------------- HMMA GEMM: BM=BN=128, BK=64, warp-staggered kk -------------
// C[M,N] = A[M,K] @ B[K,N], fp16 in, fp32 accum. 256 threads, 8 warps (2x4),
// warp tile 64x32. Stage: A 128x64 @pitch144 = 18432 B, B 64x128 @pitch272 =
// 17408 B -> 35840 B. 2 stages = 71680 B -> 2 CTAs/SM (143 KB).
// Each warp processes the 4 kk-phases of a k-tile in rotated order
// ((p + warp) & 3) so warps alternate ldsm/mma phases instead of lockstep.
#define PAB 144
#define PBB 272
#define STG4 35840
#define NST 2

__device__ __forceinline__ void load_stage(
    uint32_t sb,
    const __half* __restrict__ Ah,
    const __half* __restrict__ Bh, int K, int N, int tid)
{
    // A tile 128x64: 1024 chunks
    #pragma unroll
    for (int it = 0; it < 4; it++) {
        int idx = it * 256 + tid;
        int r = idx >> 3, c8 = idx & 7;
        cp16(sb + r * PAB + c8 * 16, Ah + (size_t)r * K + c8 * 8);
    }
    // B tile 64x128: 1024 chunks
    #pragma unroll
    for (int it = 0; it < 4; it++) {
        int idx = it * 256 + tid;
        int r = idx >> 4, c16 = idx & 15;
        cp16(sb + 18432 + r * PBB + c16 * 16, Bh + (size_t)r * N + c16 * 8);
    }
}

// EPI: 0 plain fp32 | 1 bias+relu -> fp16 | 2 bias -> fp32 | 3 plain -> fp16
template<int EPI>
__global__ __launch_bounds__(256, 2)
void hgemm4_kernel(int M, int N, int K,
                   const __half* __restrict__ Ah,
                   const __half* __restrict__ Bh,
                   const float* __restrict__ bias,
                   float* __restrict__ C,
                   __half* __restrict__ Ch)
{
    extern __shared__ __align__(16) char smem[];
    uint32_t sb = (uint32_t)__cvta_generic_to_shared(smem);

    int tid  = threadIdx.x;
    int lane = tid & 31;
    int warp = tid >> 5;
    int wm = warp & 1;
    int wn = warp >> 1;
    int row0 = blockIdx.y * 128;
    int col0 = blockIdx.x * 128;

    const __half* Ahb = Ah + (size_t)row0 * K;
    const __half* Bhb = Bh + col0;

    float acc[4][4][4];
    #pragma unroll
    for (int i = 0; i < 4; i++)
        #pragma unroll
        for (int j = 0; j < 4; j++)
            #pragma unroll
            for (int c = 0; c < 4; c++) acc[i][j][c] = 0.f;

    int NT = K / 64;

    // prologue: stage 0
    load_stage(sb, Ahb, Bhb, K, N, tid);
    CP_COMMIT();

    for (int kt = 0; kt < NT; kt++) {
        CP_WAIT0();
        __syncthreads();

        int nk = kt + 1;
        if (nk < NT) {
            load_stage(sb + (nk & 1) * STG4, Ahb + nk * 64,
                       Bhb + (size_t)(nk * 64) * N, K, N, tid);
            CP_COMMIT();
        }

        uint32_t st = sb + (kt & 1) * STG4;
        #pragma unroll
        for (int p = 0; p < 4; p++) {
            int kk = ((p + warp) & 3) * 16;      // warp-staggered phase
            uint32_t ahi[4][4], bfr[4][2];

            #pragma unroll
            for (int mi = 0; mi < 4; mi++) {
                int r = wm * 64 + mi * 16 + (lane & 15);
                int c = kk + (lane >> 4) * 8;
                LDSM_X4(ahi[mi][0], ahi[mi][1], ahi[mi][2], ahi[mi][3], st + r * PAB + c * 2);
            }
            #pragma unroll
            for (int nb2 = 0; nb2 < 2; nb2++) {
                int r = kk + (lane & 15);
                int c = wn * 32 + nb2 * 16 + (lane >> 4) * 8;
                uint32_t bh = st + 18432 + r * PBB + c * 2;
                LDSM_X4_T(bfr[nb2*2][0], bfr[nb2*2][1], bfr[nb2*2+1][0], bfr[nb2*2+1][1], bh);
            }

            #pragma unroll
            for (int mi = 0; mi < 4; mi++)
                #pragma unroll
                for (int ni = 0; ni < 4; ni++)
                    MMAH(acc[mi][ni], ahi[mi][0], ahi[mi][1], ahi[mi][2], ahi[mi][3],
                         bfr[ni][0], bfr[ni][1]);
        }
    }

    // epilogue
    int g = lane >> 2, t = lane & 3;
    #pragma unroll
    for (int mi = 0; mi < 4; mi++) {
        #pragma unroll
        for (int ni = 0; ni < 4; ni++) {
            int r = row0 + wm * 64 + mi * 16 + g;
            int c = col0 + wn * 32 + ni * 8 + t * 2;
            float v0 = acc[mi][ni][0], v1 = acc[mi][ni][1];
            float v2 = acc[mi][ni][2], v3 = acc[mi][ni][3];

            if (EPI == 1 || EPI == 2) {
                float bz0 = bias[c], bz1 = bias[c + 1];
                v0 += bz0; v1 += bz1; v2 += bz0; v3 += bz1;
            }
            if (EPI == 1) {
                v0 = fmaxf(v0, 0.f); v1 = fmaxf(v1, 0.f);
                v2 = fmaxf(v2, 0.f); v3 = fmaxf(v3, 0.f);
            }

            if (EPI == 0 || EPI == 2) {
                *(float2*)&C[(size_t)r * N + c]       = make_float2(v0, v1);
                *(float2*)&C[(size_t)(r + 8) * N + c] = make_float2(v2, v3);
            } else {
                *(uint32_t*)&Ch[(size_t)r * N + c]       = pack_h2(v0, v1);
                *(uint32_t*)&Ch[(size_t)(r + 8) * N + c] = pack_h2(v2, v3);
            }
        }
    }
}

// ---------------- flash attention: fp16 single-term, cp.async ----------------
// QKV input fused layout [NR, 3*DD]; Q at col 0, K at DD, V at 2*DD.
#define QKVS (3*DD)

__device__ __forceinline__ void load_kv(uint32_t buf,
                                        const __half* __restrict__ KhB,
                                        const __half* __restrict__ VhB,
                                        int k0, int tid)
{
    #pragma unroll
    for (int it = 0; it < 4; it++) {
        int idx = it * 128 + tid;
        int r = idx >> 3, c = idx & 7;
        cp16(buf + r * 144 + c * 16,        KhB + (size_t)(k0 + r) * QKVS + c * 8);
        cp16(buf + 9216 + r * 144 + c * 16, VhB + (size_t)(k0 + r) * QKVS + c * 8);
    }
}

__global__ __launch_bounds__(128)
void attn_f16_kernel(const __half* __restrict__ QKV,
                     const int* __restrict__ vlen,
                     __half* __restrict__ Oh)
{
    __shared__ __align__(16) char smem[36864];
    uint32_t sb = (uint32_t)__cvta_generic_to_shared(smem);

    int tid  = threadIdx.x;
    int lane = tid & 31;
    int warp = tid >> 5;
    int g    = lane >> 2;
    int t    = lane & 3;

    int bh = blockIdx.y;
    int b  = bh >> 4;
    int h  = bh & 15;
    int q0 = blockIdx.x * 64;
    int vl = vlen[b];

    size_t base = (size_t)(b * SS) * QKVS + h * HD;
    const __half* QhB = QKV + base + (size_t)q0 * QKVS;
    const __half* KhB = QKV + base + DD;
    const __half* VhB = QKV + base + 2 * DD;

    // stage Q
    #pragma unroll
    for (int it = 0; it < 4; it++) {
        int idx = it * 128 + tid;
        int r = idx >> 3, c = idx & 7;
        cp16(sb + r * 144 + c * 16, QhB + (size_t)r * QKVS + c * 8);
    }
    CP_COMMIT(); CP_WAIT0();
    __syncthreads();

    uint32_t qh[4][4];
    #pragma unroll
    for (int kk = 0; kk < 4; kk++) {
        int r = warp * 16 + (lane & 15);
        int c = kk * 16 + (lane >> 4) * 8;
        LDSM_X4(qh[kk][0], qh[kk][1], qh[kk][2], qh[kk][3], sb + r * 144 + c * 2);
    }
    __syncthreads();

    float o[8][4];
    #pragma unroll
    for (int i = 0; i < 8; i++)
        #pragma unroll
        for (int c = 0; c < 4; c++) o[i][c] = 0.f;
    float m0 = -1e30f, m1 = -1e30f, l0 = 0.f, l1 = 0.f;

    int nkt = (vl + 63) >> 6;

    load_kv(sb, KhB, VhB, 0, tid);
    CP_COMMIT();

    for (int kt = 0; kt < nkt; kt++) {
        __syncthreads();
        if (kt + 1 < nkt)
            load_kv(sb + ((kt + 1) & 1) * 18432, KhB, VhB, (kt + 1) * 64, tid);
        CP_COMMIT();
        CP_WAIT1();
        __syncthreads();

        uint32_t cur = sb + (kt & 1) * 18432;
        int k0 = kt * 64;

        float s[8][4];
        #pragma unroll
        for (int i = 0; i < 8; i++)
            #pragma unroll
            for (int c = 0; c < 4; c++) s[i][c] = 0.f;

        #pragma unroll
        for (int kk = 0; kk < 4; kk++) {
            #pragma unroll
            for (int nb = 0; nb < 4; nb++) {
                int r = nb * 16 + (lane & 15);
                int c = kk * 16 + (lane >> 4) * 8;
                uint32_t kh0, kh1, kh2, kh3;
                LDSM_X4(kh0, kh1, kh2, kh3, cur + r * 144 + c * 2);
                MMAH(s[2*nb],   qh[kk][0], qh[kk][1], qh[kk][2], qh[kk][3], kh0, kh2);
                MMAH(s[2*nb+1], qh[kk][0], qh[kk][1], qh[kk][2], qh[kk][3], kh1, kh3);
            }
        }

        #pragma unroll
        for (int nb = 0; nb < 8; nb++) {
            int c0 = k0 + nb * 8 + 2 * t;
            int c1 = c0 + 1;
            s[nb][0] = (c0 < vl) ? s[nb][0] * 0.125f : -1e30f;
            s[nb][1] = (c1 < vl) ? s[nb][1] * 0.125f : -1e30f;
            s[nb][2] = (c0 < vl) ? s[nb][2] * 0.125f : -1e30f;
            s[nb][3] = (c1 < vl) ? s[nb][3] * 0.125f : -1e30f;
        }

        float tm0 = -1e30f, tm1 = -1e30f;
        #pragma unroll
        for (int nb = 0; nb < 8; nb++) {
            tm0 = fmaxf(tm0, fmaxf(s[nb][0], s[nb][1]));
            tm1 = fmaxf(tm1, fmaxf(s[nb][2], s[nb][3]));
        }
        tm0 = fmaxf(tm0, __shfl_xor_sync(0xffffffffu, tm0, 1));
        tm0 = fmaxf(tm0, __shfl_xor_sync(0xffffffffu, tm0, 2));
        tm1 = fmaxf(tm1, __shfl_xor_sync(0xffffffffu, tm1, 1));
        tm1 = fmaxf(tm1, __shfl_xor_sync(0xffffffffu, tm1, 2));

        float mn0 = fmaxf(m0, tm0);
        float mn1 = fmaxf(m1, tm1);
        float al0 = expf_fast(m0 - mn0);
        float al1 = expf_fast(m1 - mn1);

        uint32_t pA[4][4];
        float ls0 = 0.f, ls1 = 0.f;
        #pragma unroll
        for (int nb = 0; nb < 8; nb++) {
            float p0 = expf_fast(s[nb][0] - mn0);
            float p1 = expf_fast(s[nb][1] - mn0);
            float p2 = expf_fast(s[nb][2] - mn1);
            float p3 = expf_fast(s[nb][3] - mn1);
            ls0 += p0 + p1;
            ls1 += p2 + p3;
            int ks = nb >> 1;
            int hf = (nb & 1) * 2;
            pA[ks][hf + 0] = pack_h2(p0, p1);
            pA[ks][hf + 1] = pack_h2(p2, p3);
        }
        ls0 += __shfl_xor_sync(0xffffffffu, ls0, 1);
        ls0 += __shfl_xor_sync(0xffffffffu, ls0, 2);
        ls1 += __shfl_xor_sync(0xffffffffu, ls1, 1);
        ls1 += __shfl_xor_sync(0xffffffffu, ls1, 2);

        l0 = l0 * al0 + ls0;
        l1 = l1 * al1 + ls1;
        m0 = mn0;
        m1 = mn1;

        #pragma unroll
        for (int nb = 0; nb < 8; nb++) {
            o[nb][0] *= al0; o[nb][1] *= al0;
            o[nb][2] *= al1; o[nb][3] *= al1;
        }

        #pragma unroll
        for (int kk = 0; kk < 4; kk++) {
            uint32_t a0 = pA[kk][0], a1 = pA[kk][1], a2 = pA[kk][2], a3 = pA[kk][3];
            #pragma unroll
            for (int nb = 0; nb < 4; nb++) {
                int r = kk * 16 + (lane & 15);
                int c = nb * 16 + (lane >> 4) * 8;
                uint32_t vh0, vh1, vh2, vh3;
                LDSM_X4_T(vh0, vh1, vh2, vh3, cur + 9216 + r * 144 + c * 2);
                MMAH(o[2*nb],   a0, a1, a2, a3, vh0, vh1);
                MMAH(o[2*nb+1], a0, a1, a2, a3, vh2, vh3);
            }
        }
    }

    float inv0 = 1.f / l0;
    float inv1 = 1.f / l1;
    int row0g = q0 + warp * 16 + g;
    int row1g = row0g + 8;
    __half* Ohb = Oh + (size_t)(b * SS) * DD + h * HD;
    #pragma unroll
    for (int nb = 0; nb < 8; nb++) {
        int col = nb * 8 + 2 * t;
        *(uint32_t*)(Ohb + (size_t)row0g * DD + col) =
            pack_h2(o[nb][0] * inv0, o[nb][1] * inv0);
        *(uint32_t*)(Ohb + (size_t)row1g * DD + col) =
            pack_h2(o[nb][2] * inv1, o[nb][3] * inv1);
    }
}

// ---------------- fused residual + LayerNorm --------------------------------
template<int SPLIT>
__global__ __launch_bounds__(256)
void ln_kernel(const float* __restrict__ A,
               const float* __restrict__ R,
               const float* __restrict__ g,
               const float* __restrict__ be,
               float* __restrict__ out,
               __half* __restrict__ oh)
{
    int row = blockIdx.x;
    int t   = threadIdx.x;
    const float4* a4 = (const float4*)(A + (size_t)row * DD);
    const float4* r4 = (const float4*)(R + (size_t)row * DD);
    float4 av = a4[t];
    float4 rv = r4[t];
    float x0 = av.x + rv.x, x1 = av.y + rv.y, x2 = av.z + rv.z, x3 = av.w + rv.w;

    float s = x0 + x1 + x2 + x3;
    float q = x0 * x0 + x1 * x1 + x2 * x2 + x3 * x3;
    #pragma unroll
    for (int off = 16; off >= 1; off >>= 1) {
        s += __shfl_xor_sync(0xffffffffu, s, off);
        q += __shfl_xor_sync(0xffffffffu, q, off);
    }
    __shared__ float rs[8], rq[8];
    int w = t >> 5, lane = t & 31;
    if (lane == 0) { rs[w] = s; rq[w] = q; }
    __syncthreads();
    float tot = 0.f, totq = 0.f;
    #pragma unroll
    for (int i = 0; i < 8; i++) { tot += rs[i]; totq += rq[i]; }

    float mean = tot * (1.f / DD);
    float var  = totq * (1.f / DD) - mean * mean;
    float rstd = rsqrtf(var + EPSL);

    float4 gv = ((const float4*)g)[t];
    float4 bv = ((const float4*)be)[t];
    float4 ov;
    ov.x = (x0 - mean) * rstd * gv.x + bv.x;
    ov.y = (x1 - mean) * rstd * gv.y + bv.y;
    ov.z = (x2 - mean) * rstd * gv.z + bv.z;
    ov.w = (x3 - mean) * rstd * gv.w + bv.w;
    ((float4*)(out + (size_t)row * DD))[t] = ov;

    if (SPLIT) {
        uint2 uh;
        __half* hp = (__half*)&uh;
        hp[0] = __float2half_rn(ov.x);
        hp[1] = __float2half_rn(ov.y);
        hp[2] = __float2half_rn(ov.z);
        hp[3] = __float2half_rn(ov.w);
        ((uint2*)(oh + (size_t)row * DD))[t] = uh;
    }
}

// ---------------- launch ----------------------------------------------------
extern "C" void kernel_launch(void* const* d_in, const int* in_sizes, int n_in,
                              void* d_out, int out_size)
{
    const float* x   = (const float*)d_in[0];
    const int*   vl  = (const int*)  d_in[1];
    const float* Wq  = (const float*)d_in[2];
    const float* Wk  = (const float*)d_in[3];
    const float* Wv  = (const float*)d_in[4];
    const float* Wo  = (const float*)d_in[5];
    const float* W1  = (const float*)d_in[6];
    const float* b1  = (const float*)d_in[7];
    const float* W2  = (const float*)d_in[8];
    const float* b2  = (const float*)d_in[9];
    const float* g1  = (const float*)d_in[10];
    const float* be1 = (const float*)d_in[11];
    const float* g2  = (const float*)d_in[12];
    const float* be2 = (const float*)d_in[13];
    float* out = (float*)d_out;

    float *q, *k, *r;
    cudaGetSymbolAddress((void**)&q, g_q);
    cudaGetSymbolAddress((void**)&k, g_k);
    cudaGetSymbolAddress((void**)&r, g_r);

    __half *xh, *qkv, *ah, *rh, *ffh;
    cudaGetSymbolAddress((void**)&xh,  g_xh);
    cudaGetSymbolAddress((void**)&qkv, g_qkv);
    cudaGetSymbolAddress((void**)&ah,  g_ah);
    cudaGetSymbolAddress((void**)&rh,  g_rh);
    cudaGetSymbolAddress((void**)&ffh, g_ffh);

    __half *wqkv, *wo, *w1, *w2;
    cudaGetSymbolAddress((void**)&wqkv, g_wqkv);
    cudaGetSymbolAddress((void**)&wo, g_wo);
    cudaGetSymbolAddress((void**)&w1, g_w1);
    cudaGetSymbolAddress((void**)&w2, g_w2);

    int gemm_smem = NST * STG4;   // 71680
    cudaFuncSetAttribute(hgemm4_kernel<0>, cudaFuncAttributeMaxDynamicSharedMemorySize, gemm_smem);
    cudaFuncSetAttribute(hgemm4_kernel<1>, cudaFuncAttributeMaxDynamicSharedMemorySize, gemm_smem);
    cudaFuncSetAttribute(hgemm4_kernel<2>, cudaFuncAttributeMaxDynamicSharedMemorySize, gemm_smem);
    cudaFuncSetAttribute(hgemm4_kernel<3>, cudaFuncAttributeMaxDynamicSharedMemorySize, gemm_smem);

    // one-shot fp16 conversion of weights + input
    SplitArgs sa;
    sa.s[0] = {Wq, wqkv, DD*DD/1024, DD, 3*DD, 0};
    sa.s[1] = {Wk, wqkv, DD*DD/1024, DD, 3*DD, DD};
    sa.s[2] = {Wv, wqkv, DD*DD/1024, DD, 3*DD, 2*DD};
    sa.s[3] = {Wo, wo,   DD*DD/1024, DD, DD,  0};
    sa.s[4] = {W1, w1,   DD*FF/1024, FF, FF,  0};
    sa.s[5] = {W2, w2,   DD*FF/1024, DD, DD,  0};
    sa.s[6] = {x,  xh,   NR*DD/1024, DD, DD,  0};
    int nblk = 0;
    for (int i = 0; i < 7; i++) nblk += sa.s[i].nblk;
    split_all_kernel<<<nblk, 256>>>(sa);

    dim3 gQKV(3 * DD / 128, NR / 128);   // (24, 64)
    dim3 gD(DD / 128, NR / 128);         // (8, 64)
    dim3 gF(FF / 128, NR / 128);         // (32, 64)

    // fused QKV projection -> fp16 [NR, 3*DD]
    hgemm4_kernel<3><<<gQKV, 256, gemm_smem>>>(NR, 3 * DD, DD, xh, wqkv,
                                               nullptr, nullptr, qkv);

    // attention -> fp16 [NR, DD]
    attn_f16_kernel<<<dim3(SS / 64, BB * HH), 128>>>(qkv, vl, ah);

    // output projection -> q fp32
    hgemm4_kernel<0><<<gD, 256, gemm_smem>>>(NR, DD, DD, ah, wo,
                                             nullptr, q, nullptr);

    // residual + LN1 -> r fp32 + rh fp16
    ln_kernel<1><<<NR, 256>>>(q, x, g1, be1, r, rh);

    // FFN
    hgemm4_kernel<1><<<gF, 256, gemm_smem>>>(NR, FF, DD, rh, w1, b1, nullptr, ffh);
    hgemm4_kernel<2><<<gD, 256, gemm_smem>>>(NR, DD, FF, ffh, w2, b2, k, nullptr);

    // residual + LN2 -> output
    ln_kernel<0><<<NR, 256>>>(k, r, g2, be2, out, nullptr);
}

// round 13
// speedup vs baseline: 1.1346x; 1.0262x over previous
#include <cuda_runtime.h>
#include <cuda_fp16.h>
#include <math.h>
#include <stdint.h>

// Problem constants
#define BB   4
#define SS   2048
#define DD   1024
#define HH   16
#define HD   64
#define FF   4096
#define NR   (BB*SS)          // 8192 rows
#define EPSL 1e-5f

// ---------------- scratch (device globals; no allocation allowed) ----------
__device__ float g_q [NR*DD];        // Wo output + x residual (fp32)
__device__ float g_k [NR*DD];        // FF2 output + r residual (fp32)
__device__ float g_r [NR*DD];        // LN1 output fp32

// fp16 activations (single term)
__device__ __align__(16) __half g_xh  [NR*DD];
__device__ __align__(16) __half g_qkv [(size_t)NR*3*DD];   // fused QKV output
__device__ __align__(16) __half g_ah  [NR*DD];
__device__ __align__(16) __half g_rh  [NR*DD];
__device__ __align__(16) __half g_ffh [(size_t)NR*FF];

// fp16 weights. QKV concatenated along N: [DD, 3*DD]
__device__ __align__(16) __half g_wqkv[DD*3*DD];
__device__ __align__(16) __half g_wo  [DD*DD];
__device__ __align__(16) __half g_w1  [(size_t)DD*FF];
__device__ __align__(16) __half g_w2  [(size_t)DD*FF];

// ---------------- asm helpers ------------------------------------------------
#define LDSM_X4(R0,R1,R2,R3,ADDR) \
    asm volatile("ldmatrix.sync.aligned.m8n8.x4.shared.b16 {%0,%1,%2,%3},[%4];" \
        : "=r"(R0),"=r"(R1),"=r"(R2),"=r"(R3) : "r"(ADDR))

#define LDSM_X4_T(R0,R1,R2,R3,ADDR) \
    asm volatile("ldmatrix.sync.aligned.m8n8.x4.trans.shared.b16 {%0,%1,%2,%3},[%4];" \
        : "=r"(R0),"=r"(R1),"=r"(R2),"=r"(R3) : "r"(ADDR))

#define MMAH(D,A0,A1,A2,A3,B0,B1) \
    asm volatile("mma.sync.aligned.m16n8k16.row.col.f32.f16.f16.f32 " \
        "{%0,%1,%2,%3},{%4,%5,%6,%7},{%8,%9},{%0,%1,%2,%3};" \
        : "+f"(D[0]),"+f"(D[1]),"+f"(D[2]),"+f"(D[3]) \
        : "r"(A0),"r"(A1),"r"(A2),"r"(A3),"r"(B0),"r"(B1))

__device__ __forceinline__ void cp16(uint32_t dst, const void* src) {
    asm volatile("cp.async.cg.shared.global [%0],[%1],16;" :: "r"(dst), "l"(src));
}
#define CP_COMMIT() asm volatile("cp.async.commit_group;" ::: "memory")
#define CP_WAIT0()  asm volatile("cp.async.wait_group 0;" ::: "memory")
#define CP_WAIT1()  asm volatile("cp.async.wait_group 1;" ::: "memory")

__device__ __forceinline__ uint32_t pack_h2(float a, float b) {
    __half2 h = __floats2half2_rn(a, b);
    return *reinterpret_cast<uint32_t*>(&h);
}

// fast exp on the FMA pipe. x <= 0 expected. ~2e-6 rel err.
__device__ __forceinline__ float expf_fast(float x) {
    float y = fmaxf(x * 1.44269504088896f, -126.f);
    float fl = floorf(y);
    float f = y - fl;
    float p = 1.54653240e-4f;
    p = fmaf(p, f, 1.33335581e-3f);
    p = fmaf(p, f, 9.61812910e-3f);
    p = fmaf(p, f, 5.55041086e-2f);
    p = fmaf(p, f, 2.40226507e-1f);
    p = fmaf(p, f, 6.93147181e-1f);
    p = fmaf(p, f, 1.0f);
    int ei = (int)fl;
    float sc = __int_as_float((ei + 127) << 23);
    return p * sc;
}

// ---------------- one-shot fp32 -> fp16 convert, all tensors -----------------
struct SplitSeg {
    const float* src;
    __half* h;
    int nblk;         // blocks of 1024 elems
    int cols;         // source row length
    int stride;       // dst row stride
    int off;          // dst column offset
};
struct SplitArgs { SplitSeg s[7]; };

__global__ __launch_bounds__(256)
void split_all_kernel(SplitArgs a)
{
    int blk = blockIdx.x;
    int i = 0;
    while (blk >= a.s[i].nblk) { blk -= a.s[i].nblk; i++; }
    SplitSeg sg = a.s[i];

    int e   = blk * 1024 + threadIdx.x * 4;
    int row = e / sg.cols;
    int col = e - row * sg.cols;
    size_t d = (size_t)row * sg.stride + sg.off + col;

    float4 v = *(const float4*)(sg.src + (size_t)e);
    float av[4] = {v.x, v.y, v.z, v.w};
    uint2 uh;
    __half* hp = (__half*)&uh;
    #pragma unroll
    for (int j = 0; j < 4; j++) hp[j] = __float2half_rn(av[j]);
    *(uint2*)(sg.h + d) = uh;
}

// ---------------- HMMA GEMM: BM=BN=128, BK=64, warp-staggered kk -------------
// Stage: A 128x64 @pitch144 = 18432 B, B 64x128 @pitch272 = 17408 B -> 35840 B.
// 2 stages = 71680 B -> 2 CTAs/SM. Warp-staggered kk phases.
#define PAB 144
#define PBB 272
#define STG4 35840
#define NST 2

__device__ __forceinline__ void load_stage(
    uint32_t sb,
    const __half* __restrict__ Ah,
    const __half* __restrict__ Bh, int K, int N, int tid)
{
    #pragma unroll
    for (int it = 0; it < 4; it++) {
        int idx = it * 256 + tid;
        int r = idx >> 3, c8 = idx & 7;
        cp16(sb + r * PAB + c8 * 16, Ah + (size_t)r * K + c8 * 8);
    }
    #pragma unroll
    for (int it = 0; it < 4; it++) {
        int idx = it * 256 + tid;
        int r = idx >> 4, c16 = idx & 15;
        cp16(sb + 18432 + r * PBB + c16 * 16, Bh + (size_t)r * N + c16 * 8);
    }
}

// EPI: 0 (+Res) -> fp32 | 1 bias+relu -> fp16 | 2 bias (+Res) -> fp32 | 3 -> fp16
template<int EPI>
__global__ __launch_bounds__(256, 2)
void hgemm4_kernel(int M, int N, int K,
                   const __half* __restrict__ Ah,
                   const __half* __restrict__ Bh,
                   const float* __restrict__ bias,
                   const float* __restrict__ Res,
                   float* __restrict__ C,
                   __half* __restrict__ Ch)
{
    extern __shared__ __align__(16) char smem[];
    uint32_t sb = (uint32_t)__cvta_generic_to_shared(smem);

    int tid  = threadIdx.x;
    int lane = tid & 31;
    int warp = tid >> 5;
    int wm = warp & 1;
    int wn = warp >> 1;
    int row0 = blockIdx.y * 128;
    int col0 = blockIdx.x * 128;

    const __half* Ahb = Ah + (size_t)row0 * K;
    const __half* Bhb = Bh + col0;

    float acc[4][4][4];
    #pragma unroll
    for (int i = 0; i < 4; i++)
        #pragma unroll
        for (int j = 0; j < 4; j++)
            #pragma unroll
            for (int c = 0; c < 4; c++) acc[i][j][c] = 0.f;

    int NT = K / 64;

    load_stage(sb, Ahb, Bhb, K, N, tid);
    CP_COMMIT();

    for (int kt = 0; kt < NT; kt++) {
        CP_WAIT0();
        __syncthreads();

        int nk = kt + 1;
        if (nk < NT) {
            load_stage(sb + (nk & 1) * STG4, Ahb + nk * 64,
                       Bhb + (size_t)(nk * 64) * N, K, N, tid);
            CP_COMMIT();
        }

        uint32_t st = sb + (kt & 1) * STG4;
        #pragma unroll
        for (int p = 0; p < 4; p++) {
            int kk = ((p + warp) & 3) * 16;      // warp-staggered phase
            uint32_t ahi[4][4], bfr[4][2];

            #pragma unroll
            for (int mi = 0; mi < 4; mi++) {
                int r = wm * 64 + mi * 16 + (lane & 15);
                int c = kk + (lane >> 4) * 8;
                LDSM_X4(ahi[mi][0], ahi[mi][1], ahi[mi][2], ahi[mi][3], st + r * PAB + c * 2);
            }
            #pragma unroll
            for (int nb2 = 0; nb2 < 2; nb2++) {
                int r = kk + (lane & 15);
                int c = wn * 32 + nb2 * 16 + (lane >> 4) * 8;
                uint32_t bh = st + 18432 + r * PBB + c * 2;
                LDSM_X4_T(bfr[nb2*2][0], bfr[nb2*2][1], bfr[nb2*2+1][0], bfr[nb2*2+1][1], bh);
            }

            #pragma unroll
            for (int mi = 0; mi < 4; mi++)
                #pragma unroll
                for (int ni = 0; ni < 4; ni++)
                    MMAH(acc[mi][ni], ahi[mi][0], ahi[mi][1], ahi[mi][2], ahi[mi][3],
                         bfr[ni][0], bfr[ni][1]);
        }
    }

    // epilogue
    int g = lane >> 2, t = lane & 3;
    #pragma unroll
    for (int mi = 0; mi < 4; mi++) {
        #pragma unroll
        for (int ni = 0; ni < 4; ni++) {
            int r = row0 + wm * 64 + mi * 16 + g;
            int c = col0 + wn * 32 + ni * 8 + t * 2;
            float v0 = acc[mi][ni][0], v1 = acc[mi][ni][1];
            float v2 = acc[mi][ni][2], v3 = acc[mi][ni][3];

            if (EPI == 1 || EPI == 2) {
                float bz0 = bias[c], bz1 = bias[c + 1];
                v0 += bz0; v1 += bz1; v2 += bz0; v3 += bz1;
            }
            if (EPI == 1) {
                v0 = fmaxf(v0, 0.f); v1 = fmaxf(v1, 0.f);
                v2 = fmaxf(v2, 0.f); v3 = fmaxf(v3, 0.f);
            }

            if (EPI == 0 || EPI == 2) {
                // fused residual add
                float2 r0 = *(const float2*)&Res[(size_t)r * N + c];
                float2 r1 = *(const float2*)&Res[(size_t)(r + 8) * N + c];
                v0 += r0.x; v1 += r0.y; v2 += r1.x; v3 += r1.y;
                *(float2*)&C[(size_t)r * N + c]       = make_float2(v0, v1);
                *(float2*)&C[(size_t)(r + 8) * N + c] = make_float2(v2, v3);
            } else {
                *(uint32_t*)&Ch[(size_t)r * N + c]       = pack_h2(v0, v1);
                *(uint32_t*)&Ch[(size_t)(r + 8) * N + c] = pack_h2(v2, v3);
            }
        }
    }
}

// ---------------- flash attention: 128-query tiles, 256 threads --------------
// QKV input fused layout [NR, 3*DD]; Q at col 0, K at DD, V at 2*DD.
// smem: Q staged once (128x144B = 18432 B), then two 18432B KV buffers
// (K at +0, V at +9216) occupying the same 36864 B region.
#define QKVS (3*DD)

__device__ __forceinline__ void load_kv(uint32_t buf,
                                        const __half* __restrict__ KhB,
                                        const __half* __restrict__ VhB,
                                        int k0, int tid)
{
    #pragma unroll
    for (int it = 0; it < 2; it++) {
        int idx = it * 256 + tid;
        int r = idx >> 3, c = idx & 7;
        cp16(buf + r * 144 + c * 16,        KhB + (size_t)(k0 + r) * QKVS + c * 8);
        cp16(buf + 9216 + r * 144 + c * 16, VhB + (size_t)(k0 + r) * QKVS + c * 8);
    }
}

__global__ __launch_bounds__(256)
void attn_f16_kernel(const __half* __restrict__ QKV,
                     const int* __restrict__ vlen,
                     __half* __restrict__ Oh)
{
    __shared__ __align__(16) char smem[36864];
    uint32_t sb = (uint32_t)__cvta_generic_to_shared(smem);

    int tid  = threadIdx.x;
    int lane = tid & 31;
    int warp = tid >> 5;        // 0..7, each warp owns 16 query rows
    int g    = lane >> 2;
    int t    = lane & 3;

    int bh = blockIdx.y;
    int b  = bh >> 4;
    int h  = bh & 15;
    int q0 = blockIdx.x * 128;
    int vl = vlen[b];

    size_t base = (size_t)(b * SS) * QKVS + h * HD;
    const __half* QhB = QKV + base + (size_t)q0 * QKVS;
    const __half* KhB = QKV + base + DD;
    const __half* VhB = QKV + base + 2 * DD;

    // stage Q tile (128 rows x 64 cols)
    #pragma unroll
    for (int it = 0; it < 4; it++) {
        int idx = it * 256 + tid;
        int r = idx >> 3, c = idx & 7;
        cp16(sb + r * 144 + c * 16, QhB + (size_t)r * QKVS + c * 8);
    }
    CP_COMMIT(); CP_WAIT0();
    __syncthreads();

    uint32_t qh[4][4];
    #pragma unroll
    for (int kk = 0; kk < 4; kk++) {
        int r = warp * 16 + (lane & 15);
        int c = kk * 16 + (lane >> 4) * 8;
        LDSM_X4(qh[kk][0], qh[kk][1], qh[kk][2], qh[kk][3], sb + r * 144 + c * 2);
    }
    __syncthreads();    // Q frags read; smem reusable for KV

    float o[8][4];
    #pragma unroll
    for (int i = 0; i < 8; i++)
        #pragma unroll
        for (int c = 0; c < 4; c++) o[i][c] = 0.f;
    float m0 = -1e30f, m1 = -1e30f, l0 = 0.f, l1 = 0.f;

    int nkt = (vl + 63) >> 6;

    load_kv(sb, KhB, VhB, 0, tid);
    CP_COMMIT();

    for (int kt = 0; kt < nkt; kt++) {
        __syncthreads();
        if (kt + 1 < nkt)
            load_kv(sb + ((kt + 1) & 1) * 18432, KhB, VhB, (kt + 1) * 64, tid);
        CP_COMMIT();
        CP_WAIT1();
        __syncthreads();

        uint32_t cur = sb + (kt & 1) * 18432;
        int k0 = kt * 64;

        float s[8][4];
        #pragma unroll
        for (int i = 0; i < 8; i++)
            #pragma unroll
            for (int c = 0; c < 4; c++) s[i][c] = 0.f;

        #pragma unroll
        for (int kk = 0; kk < 4; kk++) {
            #pragma unroll
            for (int nb = 0; nb < 4; nb++) {
                int r = nb * 16 + (lane & 15);
                int c = kk * 16 + (lane >> 4) * 8;
                uint32_t kh0, kh1, kh2, kh3;
                LDSM_X4(kh0, kh1, kh2, kh3, cur + r * 144 + c * 2);
                MMAH(s[2*nb],   qh[kk][0], qh[kk][1], qh[kk][2], qh[kk][3], kh0, kh2);
                MMAH(s[2*nb+1], qh[kk][0], qh[kk][1], qh[kk][2], qh[kk][3], kh1, kh3);
            }
        }

        #pragma unroll
        for (int nb = 0; nb < 8; nb++) {
            int c0 = k0 + nb * 8 + 2 * t;
            int c1 = c0 + 1;
            s[nb][0] = (c0 < vl) ? s[nb][0] * 0.125f : -1e30f;
            s[nb][1] = (c1 < vl) ? s[nb][1] * 0.125f : -1e30f;
            s[nb][2] = (c0 < vl) ? s[nb][2] * 0.125f : -1e30f;
            s[nb][3] = (c1 < vl) ? s[nb][3] * 0.125f : -1e30f;
        }

        float tm0 = -1e30f, tm1 = -1e30f;
        #pragma unroll
        for (int nb = 0; nb < 8; nb++) {
            tm0 = fmaxf(tm0, fmaxf(s[nb][0], s[nb][1]));
            tm1 = fmaxf(tm1, fmaxf(s[nb][2], s[nb][3]));
        }
        tm0 = fmaxf(tm0, __shfl_xor_sync(0xffffffffu, tm0, 1));
        tm0 = fmaxf(tm0, __shfl_xor_sync(0xffffffffu, tm0, 2));
        tm1 = fmaxf(tm1, __shfl_xor_sync(0xffffffffu, tm1, 1));
        tm1 = fmaxf(tm1, __shfl_xor_sync(0xffffffffu, tm1, 2));

        float mn0 = fmaxf(m0, tm0);
        float mn1 = fmaxf(m1, tm1);
        float al0 = expf_fast(m0 - mn0);
        float al1 = expf_fast(m1 - mn1);

        uint32_t pA[4][4];
        float ls0 = 0.f, ls1 = 0.f;
        #pragma unroll
        for (int nb = 0; nb < 8; nb++) {
            float p0 = expf_fast(s[nb][0] - mn0);
            float p1 = expf_fast(s[nb][1] - mn0);
            float p2 = expf_fast(s[nb][2] - mn1);
            float p3 = expf_fast(s[nb][3] - mn1);
            ls0 += p0 + p1;
            ls1 += p2 + p3;
            int ks = nb >> 1;
            int hf = (nb & 1) * 2;
            pA[ks][hf + 0] = pack_h2(p0, p1);
            pA[ks][hf + 1] = pack_h2(p2, p3);
        }
        ls0 += __shfl_xor_sync(0xffffffffu, ls0, 1);
        ls0 += __shfl_xor_sync(0xffffffffu, ls0, 2);
        ls1 += __shfl_xor_sync(0xffffffffu, ls1, 1);
        ls1 += __shfl_xor_sync(0xffffffffu, ls1, 2);

        l0 = l0 * al0 + ls0;
        l1 = l1 * al1 + ls1;
        m0 = mn0;
        m1 = mn1;

        #pragma unroll
        for (int nb = 0; nb < 8; nb++) {
            o[nb][0] *= al0; o[nb][1] *= al0;
            o[nb][2] *= al1; o[nb][3] *= al1;
        }

        #pragma unroll
        for (int kk = 0; kk < 4; kk++) {
            uint32_t a0 = pA[kk][0], a1 = pA[kk][1], a2 = pA[kk][2], a3 = pA[kk][3];
            #pragma unroll
            for (int nb = 0; nb < 4; nb++) {
                int r = kk * 16 + (lane & 15);
                int c = nb * 16 + (lane >> 4) * 8;
                uint32_t vh0, vh1, vh2, vh3;
                LDSM_X4_T(vh0, vh1, vh2, vh3, cur + 9216 + r * 144 + c * 2);
                MMAH(o[2*nb],   a0, a1, a2, a3, vh0, vh1);
                MMAH(o[2*nb+1], a0, a1, a2, a3, vh2, vh3);
            }
        }
    }

    float inv0 = 1.f / l0;
    float inv1 = 1.f / l1;
    int row0g = q0 + warp * 16 + g;
    int row1g = row0g + 8;
    __half* Ohb = Oh + (size_t)(b * SS) * DD + h * HD;
    #pragma unroll
    for (int nb = 0; nb < 8; nb++) {
        int col = nb * 8 + 2 * t;
        *(uint32_t*)(Ohb + (size_t)row0g * DD + col) =
            pack_h2(o[nb][0] * inv0, o[nb][1] * inv0);
        *(uint32_t*)(Ohb + (size_t)row1g * DD + col) =
            pack_h2(o[nb][2] * inv1, o[nb][3] * inv1);
    }
}

// ---------------- fused LayerNorm (input already contains residual) ----------
template<int SPLIT>
__global__ __launch_bounds__(256)
void ln_kernel(const float* __restrict__ A,
               const float* __restrict__ g,
               const float* __restrict__ be,
               float* __restrict__ out,
               __half* __restrict__ oh)
{
    int row = blockIdx.x;
    int t   = threadIdx.x;
    float4 av = ((const float4*)(A + (size_t)row * DD))[t];
    float x0 = av.x, x1 = av.y, x2 = av.z, x3 = av.w;

    float s = x0 + x1 + x2 + x3;
    float q = x0 * x0 + x1 * x1 + x2 * x2 + x3 * x3;
    #pragma unroll
    for (int off = 16; off >= 1; off >>= 1) {
        s += __shfl_xor_sync(0xffffffffu, s, off);
        q += __shfl_xor_sync(0xffffffffu, q, off);
    }
    __shared__ float rs[8], rq[8];
    int w = t >> 5, lane = t & 31;
    if (lane == 0) { rs[w] = s; rq[w] = q; }
    __syncthreads();
    float tot = 0.f, totq = 0.f;
    #pragma unroll
    for (int i = 0; i < 8; i++) { tot += rs[i]; totq += rq[i]; }

    float mean = tot * (1.f / DD);
    float var  = totq * (1.f / DD) - mean * mean;
    float rstd = rsqrtf(var + EPSL);

    float4 gv = ((const float4*)g)[t];
    float4 bv = ((const float4*)be)[t];
    float4 ov;
    ov.x = (x0 - mean) * rstd * gv.x + bv.x;
    ov.y = (x1 - mean) * rstd * gv.y + bv.y;
    ov.z = (x2 - mean) * rstd * gv.z + bv.z;
    ov.w = (x3 - mean) * rstd * gv.w + bv.w;
    ((float4*)(out + (size_t)row * DD))[t] = ov;

    if (SPLIT) {
        uint2 uh;
        __half* hp = (__half*)&uh;
        hp[0] = __float2half_rn(ov.x);
        hp[1] = __float2half_rn(ov.y);
        hp[2] = __float2half_rn(ov.z);
        hp[3] = __float2half_rn(ov.w);
        ((uint2*)(oh + (size_t)row * DD))[t] = uh;
    }
}

// ---------------- launch ----------------------------------------------------
extern "C" void kernel_launch(void* const* d_in, const int* in_sizes, int n_in,
                              void* d_out, int out_size)
{
    const float* x   = (const float*)d_in[0];
    const int*   vl  = (const int*)  d_in[1];
    const float* Wq  = (const float*)d_in[2];
    const float* Wk  = (const float*)d_in[3];
    const float* Wv  = (const float*)d_in[4];
    const float* Wo  = (const float*)d_in[5];
    const float* W1  = (const float*)d_in[6];
    const float* b1  = (const float*)d_in[7];
    const float* W2  = (const float*)d_in[8];
    const float* b2  = (const float*)d_in[9];
    const float* g1  = (const float*)d_in[10];
    const float* be1 = (const float*)d_in[11];
    const float* g2  = (const float*)d_in[12];
    const float* be2 = (const float*)d_in[13];
    float* out = (float*)d_out;

    float *q, *k, *r;
    cudaGetSymbolAddress((void**)&q, g_q);
    cudaGetSymbolAddress((void**)&k, g_k);
    cudaGetSymbolAddress((void**)&r, g_r);

    __half *xh, *qkv, *ah, *rh, *ffh;
    cudaGetSymbolAddress((void**)&xh,  g_xh);
    cudaGetSymbolAddress((void**)&qkv, g_qkv);
    cudaGetSymbolAddress((void**)&ah,  g_ah);
    cudaGetSymbolAddress((void**)&rh,  g_rh);
    cudaGetSymbolAddress((void**)&ffh, g_ffh);

    __half *wqkv, *wo, *w1, *w2;
    cudaGetSymbolAddress((void**)&wqkv, g_wqkv);
    cudaGetSymbolAddress((void**)&wo, g_wo);
    cudaGetSymbolAddress((void**)&w1, g_w1);
    cudaGetSymbolAddress((void**)&w2, g_w2);

    int gemm_smem = NST * STG4;   // 71680
    cudaFuncSetAttribute(hgemm4_kernel<0>, cudaFuncAttributeMaxDynamicSharedMemorySize, gemm_smem);
    cudaFuncSetAttribute(hgemm4_kernel<1>, cudaFuncAttributeMaxDynamicSharedMemorySize, gemm_smem);
    cudaFuncSetAttribute(hgemm4_kernel<2>, cudaFuncAttributeMaxDynamicSharedMemorySize, gemm_smem);
    cudaFuncSetAttribute(hgemm4_kernel<3>, cudaFuncAttributeMaxDynamicSharedMemorySize, gemm_smem);

    // one-shot fp16 conversion of weights + input
    SplitArgs sa;
    sa.s[0] = {Wq, wqkv, DD*DD/1024, DD, 3*DD, 0};
    sa.s[1] = {Wk, wqkv, DD*DD/1024, DD, 3*DD, DD};
    sa.s[2] = {Wv, wqkv, DD*DD/1024, DD, 3*DD, 2*DD};
    sa.s[3] = {Wo, wo,   DD*DD/1024, DD, DD,  0};
    sa.s[4] = {W1, w1,   DD*FF/1024, FF, FF,  0};
    sa.s[5] = {W2, w2,   DD*FF/1024, DD, DD,  0};
    sa.s[6] = {x,  xh,   NR*DD/1024, DD, DD,  0};
    int nblk = 0;
    for (int i = 0; i < 7; i++) nblk += sa.s[i].nblk;
    split_all_kernel<<<nblk, 256>>>(sa);

    dim3 gQKV(3 * DD / 128, NR / 128);   // (24, 64)
    dim3 gD(DD / 128, NR / 128);         // (8, 64)
    dim3 gF(FF / 128, NR / 128);         // (32, 64)

    // fused QKV projection -> fp16 [NR, 3*DD]
    hgemm4_kernel<3><<<gQKV, 256, gemm_smem>>>(NR, 3 * DD, DD, xh, wqkv,
                                               nullptr, nullptr, nullptr, qkv);

    // attention -> fp16 [NR, DD]  (128-query tiles)
    attn_f16_kernel<<<dim3(SS / 128, BB * HH), 256>>>(qkv, vl, ah);

    // output projection + residual x -> q fp32
    hgemm4_kernel<0><<<gD, 256, gemm_smem>>>(NR, DD, DD, ah, wo,
                                             nullptr, x, q, nullptr);

    // LN1 -> r fp32 + rh fp16
    ln_kernel<1><<<NR, 256>>>(q, g1, be1, r, rh);

    // FFN
    hgemm4_kernel<1><<<gF, 256, gemm_smem>>>(NR, FF, DD, rh, w1, b1,
                                             nullptr, nullptr, ffh);
    hgemm4_kernel<2><<<gD, 256, gemm_smem>>>(NR, DD, FF, ffh, w2, b2,
                                             r, k, nullptr);

    // LN2 -> output
    ln_kernel<0><<<NR, 256>>>(k, g2, be2, out, nullptr);
}